// round 2
// baseline (speedup 1.0000x reference)
#include <cuda_runtime.h>
#include <cuda_bf16.h>
#include <cstddef>

// Problem dims (fixed by the reference)
#define Bn 8
#define Cn 256
#define Nn 4096
#define SPLITS 8

// -------- scratch (no allocations allowed; __device__ globals) -----------
__device__ float g_F[Bn * Cn * Nn];                 // 32 MB
__device__ float g_G[Bn * Cn * Nn];                 // 32 MB
__device__ float g_H[Bn * Cn * Nn];                 // 32 MB
__device__ float g_attn[Bn * Cn * Nn];              // 32 MB
__device__ float g_sPart[SPLITS * Bn * Cn * Cn];    // 16 MB
__device__ float g_beta[Bn * Cn * Cn];              // 2 MB

// ---------------- shared 8x8 microtile FFMA core -------------------------
__device__ __forceinline__ void mm_inner(const float (*As)[128],
                                         const float (*Bs)[128],
                                         float acc[8][8], int tx, int ty) {
#pragma unroll
    for (int k = 0; k < 8; ++k) {
        float4 a0 = *(const float4*)&As[k][ty * 8];
        float4 a1 = *(const float4*)&As[k][ty * 8 + 4];
        float4 b0 = *(const float4*)&Bs[k][tx * 8];
        float4 b1 = *(const float4*)&Bs[k][tx * 8 + 4];
        float a[8] = {a0.x, a0.y, a0.z, a0.w, a1.x, a1.y, a1.z, a1.w};
        float b[8] = {b0.x, b0.y, b0.z, b0.w, b1.x, b1.y, b1.z, b1.w};
#pragma unroll
        for (int i = 0; i < 8; ++i)
#pragma unroll
            for (int j = 0; j < 8; ++j)
                acc[i][j] += a[i] * b[j];
    }
}

// ---------------- Stage A/E: Y[b][m][n] = sum_k W[m][k] X[b][k][n] + bias[m]
// grid: (Nn/128, Cn/128, Bn), 256 threads
__global__ __launch_bounds__(256, 2)
void gemm_conv(const float* __restrict__ W, const float* __restrict__ bias,
               const float* __restrict__ X, float* __restrict__ Y) {
    const int b = blockIdx.z;
    const float* Xb = X + (size_t)b * Cn * Nn;
    float* Yb = Y + (size_t)b * Cn * Nn;
    const int n0 = blockIdx.x * 128;
    const int m0 = blockIdx.y * 128;

    __shared__ __align__(16) float As[8][128];
    __shared__ __align__(16) float Bs[8][128];

    const int tid = threadIdx.x;
    const int tx = tid % 16;
    const int ty = tid / 16;
    float acc[8][8] = {};

    const int mA = tid >> 1;            // 0..127
    const int kA = (tid & 1) * 4;       // 0 or 4
    const int kB = tid >> 5;            // 0..7
    const int nB = (tid & 31) * 4;      // 0..124

    for (int k0 = 0; k0 < Cn; k0 += 8) {
        float4 a4 = *(const float4*)(W + (size_t)(m0 + mA) * Cn + k0 + kA);
        As[kA + 0][mA] = a4.x;
        As[kA + 1][mA] = a4.y;
        As[kA + 2][mA] = a4.z;
        As[kA + 3][mA] = a4.w;
        *(float4*)&Bs[kB][nB] =
            *(const float4*)(Xb + (size_t)(k0 + kB) * Nn + n0 + nB);
        __syncthreads();
        mm_inner(As, Bs, acc, tx, ty);
        __syncthreads();
    }

#pragma unroll
    for (int i = 0; i < 8; ++i) {
        const int m = m0 + ty * 8 + i;
        const float bi = bias[m];
        float4 v0 = make_float4(acc[i][0] + bi, acc[i][1] + bi,
                                acc[i][2] + bi, acc[i][3] + bi);
        float4 v1 = make_float4(acc[i][4] + bi, acc[i][5] + bi,
                                acc[i][6] + bi, acc[i][7] + bi);
        float* p = Yb + (size_t)m * Nn + n0 + tx * 8;
        *(float4*)p = v0;
        *(float4*)(p + 4) = v1;
    }
}

// ---------------- Stage B: s[b][i][j] = sum_n G[n*C+i] F[n*C+j], split-K
// grid: (Cn/128, Cn/128, Bn*SPLITS), 256 threads
__global__ __launch_bounds__(256, 2)
void gemm_s_kernel() {
    const int sp = blockIdx.z % SPLITS;
    const int b = blockIdx.z / SPLITS;
    const float* Gb = g_G + (size_t)b * Cn * Nn;
    const float* Fb = g_F + (size_t)b * Cn * Nn;
    const int j0 = blockIdx.x * 128;
    const int i0 = blockIdx.y * 128;

    __shared__ __align__(16) float As[8][128];
    __shared__ __align__(16) float Bs[8][128];

    const int tid = threadIdx.x;
    const int tx = tid % 16;
    const int ty = tid / 16;
    float acc[8][8] = {};

    const int kB = tid >> 5;        // 0..7
    const int cB = (tid & 31) * 4;  // 0..124
    const int nbase = sp * (Nn / SPLITS);

    for (int k0 = 0; k0 < Nn / SPLITS; k0 += 8) {
        const size_t rowoff = (size_t)(nbase + k0 + kB) * Cn;
        *(float4*)&As[kB][cB] = *(const float4*)(Gb + rowoff + i0 + cB);
        *(float4*)&Bs[kB][cB] = *(const float4*)(Fb + rowoff + j0 + cB);
        __syncthreads();
        mm_inner(As, Bs, acc, tx, ty);
        __syncthreads();
    }

    float* out = g_sPart + ((size_t)(sp * Bn + b) * Cn) * Cn;
#pragma unroll
    for (int i = 0; i < 8; ++i) {
        float* p = out + (size_t)(i0 + ty * 8 + i) * Cn + j0 + tx * 8;
        *(float4*)p = make_float4(acc[i][0], acc[i][1], acc[i][2], acc[i][3]);
        *(float4*)(p + 4) =
            make_float4(acc[i][4], acc[i][5], acc[i][6], acc[i][7]);
    }
}

// ---------------- Stage C: reduce split-K partials + row softmax
// grid: Bn*Cn blocks, 256 threads (one per j)
__global__ __launch_bounds__(256)
void softmax_kernel() {
    const int row = blockIdx.x;  // b*Cn + i
    const int j = threadIdx.x;

    float v = 0.f;
#pragma unroll
    for (int sp = 0; sp < SPLITS; ++sp)
        v += g_sPart[((size_t)sp * Bn * Cn + row) * Cn + j];

    __shared__ float red[256];
    red[j] = v;
    __syncthreads();
    for (int s = 128; s > 0; s >>= 1) {
        if (j < s) red[j] = fmaxf(red[j], red[j + s]);
        __syncthreads();
    }
    const float mx = red[0];
    __syncthreads();
    const float e = expf(v - mx);
    red[j] = e;
    __syncthreads();
    for (int s = 128; s > 0; s >>= 1) {
        if (j < s) red[j] += red[j + s];
        __syncthreads();
    }
    g_beta[(size_t)row * Cn + j] = e / red[0];
}

// ---------------- Stage D: attn[b][i][n] = sum_j beta[b][i][j] * H[n*C+j]
// grid: (Nn/128, Cn/128, Bn), 256 threads
__global__ __launch_bounds__(256, 2)
void gemm_out_kernel() {
    const int b = blockIdx.z;
    const float* Hb = g_H + (size_t)b * Cn * Nn;
    const float* Beta = g_beta + (size_t)b * Cn * Cn;
    float* Ab = g_attn + (size_t)b * Cn * Nn;
    const int n0 = blockIdx.x * 128;
    const int i0 = blockIdx.y * 128;

    __shared__ __align__(16) float As[8][128];
    __shared__ __align__(16) float Bs[8][128];

    const int tid = threadIdx.x;
    const int tx = tid % 16;
    const int ty = tid / 16;
    float acc[8][8] = {};

    const int rA = tid >> 1;       // 0..127 (row for A, n for B)
    const int kA = (tid & 1) * 4;  // 0 or 4

    for (int j0k = 0; j0k < Cn; j0k += 8) {
        float4 a4 = *(const float4*)(Beta + (size_t)(i0 + rA) * Cn + j0k + kA);
        As[kA + 0][rA] = a4.x;
        As[kA + 1][rA] = a4.y;
        As[kA + 2][rA] = a4.z;
        As[kA + 3][rA] = a4.w;
        float4 b4 = *(const float4*)(Hb + (size_t)(n0 + rA) * Cn + j0k + kA);
        Bs[kA + 0][rA] = b4.x;
        Bs[kA + 1][rA] = b4.y;
        Bs[kA + 2][rA] = b4.z;
        Bs[kA + 3][rA] = b4.w;
        __syncthreads();
        mm_inner(As, Bs, acc, tx, ty);
        __syncthreads();
    }

#pragma unroll
    for (int i = 0; i < 8; ++i) {
        float* p = Ab + (size_t)(i0 + ty * 8 + i) * Nn + n0 + tx * 8;
        *(float4*)p = make_float4(acc[i][0], acc[i][1], acc[i][2], acc[i][3]);
        *(float4*)(p + 4) =
            make_float4(acc[i][4], acc[i][5], acc[i][6], acc[i][7]);
    }
}

// -------------------------------------------------------------------------
extern "C" void kernel_launch(void* const* d_in, const int* in_sizes, int n_in,
                              void* d_out, int out_size) {
    const float* x = (const float*)d_in[0];
    const float* Wf = (const float*)d_in[1];
    const float* bf = (const float*)d_in[2];
    const float* Wg = (const float*)d_in[3];
    const float* bg = (const float*)d_in[4];
    const float* Wh = (const float*)d_in[5];
    const float* bh = (const float*)d_in[6];
    const float* Wo = (const float*)d_in[7];
    const float* bo = (const float*)d_in[8];
    float* out = (float*)d_out;

    float *pF, *pG, *pH, *pA;
    cudaGetSymbolAddress((void**)&pF, g_F);
    cudaGetSymbolAddress((void**)&pG, g_G);
    cudaGetSymbolAddress((void**)&pH, g_H);
    cudaGetSymbolAddress((void**)&pA, g_attn);

    dim3 gconv(Nn / 128, Cn / 128, Bn);
    gemm_conv<<<gconv, 256>>>(Wf, bf, x, pF);
    gemm_conv<<<gconv, 256>>>(Wg, bg, x, pG);
    gemm_conv<<<gconv, 256>>>(Wh, bh, x, pH);
    gemm_s_kernel<<<dim3(Cn / 128, Cn / 128, Bn * SPLITS), 256>>>();
    softmax_kernel<<<Bn * Cn, 256>>>();
    gemm_out_kernel<<<dim3(Nn / 128, Cn / 128, Bn), 256>>>();
    gemm_conv<<<gconv, 256>>>(Wo, bo, pA, out);
}

// round 3
// speedup vs baseline: 1.1041x; 1.1041x over previous
#include <cuda_runtime.h>
#include <cuda_bf16.h>
#include <cstddef>

// Problem dims (fixed by the reference)
#define Bn 8
#define Cn 256
#define Nn 4096
#define SPLITS 8
#define KT 16   // K-tile depth

typedef unsigned long long u64;

// -------- scratch (no allocations allowed; __device__ globals) -----------
__device__ float g_F[Bn * Cn * Nn];
__device__ float g_G[Bn * Cn * Nn];
__device__ float g_H[Bn * Cn * Nn];
__device__ float g_attn[Bn * Cn * Nn];
__device__ float g_sPart[SPLITS * Bn * Cn * Cn];
__device__ float g_beta[Bn * Cn * Cn];

// ---------------- packed f32x2 helpers (Blackwell) ------------------------
__device__ __forceinline__ u64 pk2(float x) {
    u64 r;
    asm("mov.b64 %0, {%1, %1};" : "=l"(r) : "f"(x));
    return r;
}
__device__ __forceinline__ void fma2(u64& d, u64 a, u64 b) {
    asm("fma.rn.f32x2 %0, %1, %2, %0;" : "+l"(d) : "l"(a), "l"(b));
}
__device__ __forceinline__ float2 unpk(u64 v) {
    float2 r;
    asm("mov.b64 {%0, %1}, %2;" : "=f"(r.x), "=f"(r.y) : "l"(v));
    return r;
}

// ---------------- 16-deep 8x8 microtile core (f32x2) ----------------------
__device__ __forceinline__ void mm16(const float (*As)[128],
                                     const float (*Bs)[128],
                                     u64 acc[8][4], int tx, int ty) {
#pragma unroll
    for (int k = 0; k < KT; ++k) {
        float4 a0 = *(const float4*)&As[k][ty * 8];
        float4 a1 = *(const float4*)&As[k][ty * 8 + 4];
        longlong2 c0 = *(const longlong2*)&Bs[k][tx * 8];
        longlong2 c1 = *(const longlong2*)&Bs[k][tx * 8 + 4];
        u64 b2[4] = {(u64)c0.x, (u64)c0.y, (u64)c1.x, (u64)c1.y};
        float a[8] = {a0.x, a0.y, a0.z, a0.w, a1.x, a1.y, a1.z, a1.w};
#pragma unroll
        for (int i = 0; i < 8; ++i) {
            u64 ai = pk2(a[i]);
            fma2(acc[i][0], ai, b2[0]);
            fma2(acc[i][1], ai, b2[1]);
            fma2(acc[i][2], ai, b2[2]);
            fma2(acc[i][3], ai, b2[3]);
        }
    }
}

__device__ __forceinline__ void st_row(float* p, const u64* ar, float bi) {
    float2 v0 = unpk(ar[0]), v1 = unpk(ar[1]);
    float2 v2 = unpk(ar[2]), v3 = unpk(ar[3]);
    *(float4*)p = make_float4(v0.x + bi, v0.y + bi, v1.x + bi, v1.y + bi);
    *(float4*)(p + 4) = make_float4(v2.x + bi, v2.y + bi, v3.x + bi, v3.y + bi);
}

// ---------------- Stage A/E: Y[b][m][n] = sum_k W[m][k] X[b][k][n] + bias[m]
// grid: (Nn/128, Cn/128, Bn), 256 threads
__global__ __launch_bounds__(256, 2)
void gemm_conv(const float* __restrict__ W, const float* __restrict__ bias,
               const float* __restrict__ X, float* __restrict__ Y) {
    const int b = blockIdx.z;
    const float* Xb = X + (size_t)b * Cn * Nn;
    float* Yb = Y + (size_t)b * Cn * Nn;
    const int n0 = blockIdx.x * 128;
    const int m0 = blockIdx.y * 128;

    __shared__ __align__(16) float As[2][KT][128];
    __shared__ __align__(16) float Bs[2][KT][128];

    const int tid = threadIdx.x;
    const int tx = tid % 16;
    const int ty = tid / 16;
    // A loader: transpose scatter W[m][k] -> As[k][m]
    const int mA = tid >> 1;
    const int kAo = (tid & 1) * 8;
    // B loader: direct rows
    const int kB = tid >> 4;
    const int nB = (tid & 15) * 8;

    u64 acc[8][4] = {};
    float4 a0, a1, b0, b1;

#define LOADG_CONV(k0)                                                        \
    {                                                                         \
        const float* wp = W + (size_t)(m0 + mA) * Cn + (k0) + kAo;            \
        a0 = *(const float4*)wp;                                              \
        a1 = *(const float4*)(wp + 4);                                        \
        const float* xp = Xb + (size_t)((k0) + kB) * Nn + n0 + nB;            \
        b0 = *(const float4*)xp;                                              \
        b1 = *(const float4*)(xp + 4);                                        \
    }
#define STORES_CONV(bf)                                                       \
    {                                                                         \
        As[bf][kAo + 0][mA] = a0.x; As[bf][kAo + 1][mA] = a0.y;               \
        As[bf][kAo + 2][mA] = a0.z; As[bf][kAo + 3][mA] = a0.w;               \
        As[bf][kAo + 4][mA] = a1.x; As[bf][kAo + 5][mA] = a1.y;               \
        As[bf][kAo + 6][mA] = a1.z; As[bf][kAo + 7][mA] = a1.w;               \
        *(float4*)&Bs[bf][kB][nB] = b0;                                       \
        *(float4*)&Bs[bf][kB][nB + 4] = b1;                                   \
    }

    LOADG_CONV(0);
    STORES_CONV(0);
    __syncthreads();
    int buf = 0;
    for (int k0 = KT; k0 < Cn; k0 += KT) {
        LOADG_CONV(k0);
        mm16(As[buf], Bs[buf], acc, tx, ty);
        STORES_CONV(buf ^ 1);
        __syncthreads();
        buf ^= 1;
    }
    mm16(As[buf], Bs[buf], acc, tx, ty);

#pragma unroll
    for (int i = 0; i < 8; ++i) {
        const int m = m0 + ty * 8 + i;
        st_row(Yb + (size_t)m * Nn + n0 + tx * 8, acc[i], bias[m]);
    }
}

// ---------------- Stage B: s[b][i][j] = sum_n G[n*C+i] F[n*C+j], split-K
// grid: (Cn/128, Cn/128, Bn*SPLITS), 256 threads
__global__ __launch_bounds__(256, 2)
void gemm_s_kernel() {
    const int sp = blockIdx.z % SPLITS;
    const int b = blockIdx.z / SPLITS;
    const float* Gb = g_G + (size_t)b * Cn * Nn;
    const float* Fb = g_F + (size_t)b * Cn * Nn;
    const int j0 = blockIdx.x * 128;
    const int i0 = blockIdx.y * 128;

    __shared__ __align__(16) float As[2][KT][128];
    __shared__ __align__(16) float Bs[2][KT][128];

    const int tid = threadIdx.x;
    const int tx = tid % 16;
    const int ty = tid / 16;
    const int kB = tid >> 4;
    const int cB = (tid & 15) * 8;
    const int nbase = sp * (Nn / SPLITS);

    u64 acc[8][4] = {};
    float4 a0, a1, b0, b1;

#define LOADG_S(k0)                                                           \
    {                                                                         \
        const size_t ro = (size_t)(nbase + (k0) + kB) * Cn;                   \
        const float* gp = Gb + ro + i0 + cB;                                  \
        a0 = *(const float4*)gp; a1 = *(const float4*)(gp + 4);               \
        const float* fp = Fb + ro + j0 + cB;                                  \
        b0 = *(const float4*)fp; b1 = *(const float4*)(fp + 4);               \
    }
#define STORES_S(bf)                                                          \
    {                                                                         \
        *(float4*)&As[bf][kB][cB] = a0; *(float4*)&As[bf][kB][cB + 4] = a1;   \
        *(float4*)&Bs[bf][kB][cB] = b0; *(float4*)&Bs[bf][kB][cB + 4] = b1;   \
    }

    LOADG_S(0);
    STORES_S(0);
    __syncthreads();
    int buf = 0;
    for (int k0 = KT; k0 < Nn / SPLITS; k0 += KT) {
        LOADG_S(k0);
        mm16(As[buf], Bs[buf], acc, tx, ty);
        STORES_S(buf ^ 1);
        __syncthreads();
        buf ^= 1;
    }
    mm16(As[buf], Bs[buf], acc, tx, ty);

    float* out = g_sPart + ((size_t)(sp * Bn + b) * Cn) * Cn;
#pragma unroll
    for (int i = 0; i < 8; ++i)
        st_row(out + (size_t)(i0 + ty * 8 + i) * Cn + j0 + tx * 8, acc[i], 0.f);
}

// ---------------- Stage C: reduce split-K partials + row softmax
__global__ __launch_bounds__(256)
void softmax_kernel() {
    const int row = blockIdx.x;  // b*Cn + i
    const int j = threadIdx.x;

    float v = 0.f;
#pragma unroll
    for (int sp = 0; sp < SPLITS; ++sp)
        v += g_sPart[((size_t)sp * Bn * Cn + row) * Cn + j];

    __shared__ float red[256];
    red[j] = v;
    __syncthreads();
    for (int s = 128; s > 0; s >>= 1) {
        if (j < s) red[j] = fmaxf(red[j], red[j + s]);
        __syncthreads();
    }
    const float mx = red[0];
    __syncthreads();
    const float e = expf(v - mx);
    red[j] = e;
    __syncthreads();
    for (int s = 128; s > 0; s >>= 1) {
        if (j < s) red[j] += red[j + s];
        __syncthreads();
    }
    g_beta[(size_t)row * Cn + j] = e / red[0];
}

// ---------------- Stage D: attn[b][i][n] = sum_j beta[b][i][j] * H[n*C+j]
// grid: (Nn/128, Cn/128, Bn), 256 threads
__global__ __launch_bounds__(256, 2)
void gemm_out_kernel() {
    const int b = blockIdx.z;
    const float* Hb = g_H + (size_t)b * Cn * Nn;
    const float* Beta = g_beta + (size_t)b * Cn * Cn;
    float* Ab = g_attn + (size_t)b * Cn * Nn;
    const int n0 = blockIdx.x * 128;
    const int i0 = blockIdx.y * 128;

    __shared__ __align__(16) float As[2][KT][128];
    __shared__ __align__(16) float Bs[2][KT][128];

    const int tid = threadIdx.x;
    const int tx = tid % 16;
    const int ty = tid / 16;
    const int rA = tid >> 1;        // row index for both transposed loads
    const int kAo = (tid & 1) * 8;  // 0 or 8

    u64 acc[8][4] = {};
    float4 a0, a1, b0, b1;

#define LOADG_O(k0)                                                           \
    {                                                                         \
        const float* bp = Beta + (size_t)(i0 + rA) * Cn + (k0) + kAo;         \
        a0 = *(const float4*)bp; a1 = *(const float4*)(bp + 4);               \
        const float* hp = Hb + (size_t)(n0 + rA) * Cn + (k0) + kAo;          \
        b0 = *(const float4*)hp; b1 = *(const float4*)(hp + 4);               \
    }
#define STORES_O(bf)                                                          \
    {                                                                         \
        As[bf][kAo + 0][rA] = a0.x; As[bf][kAo + 1][rA] = a0.y;               \
        As[bf][kAo + 2][rA] = a0.z; As[bf][kAo + 3][rA] = a0.w;               \
        As[bf][kAo + 4][rA] = a1.x; As[bf][kAo + 5][rA] = a1.y;               \
        As[bf][kAo + 6][rA] = a1.z; As[bf][kAo + 7][rA] = a1.w;               \
        Bs[bf][kAo + 0][rA] = b0.x; Bs[bf][kAo + 1][rA] = b0.y;               \
        Bs[bf][kAo + 2][rA] = b0.z; Bs[bf][kAo + 3][rA] = b0.w;               \
        Bs[bf][kAo + 4][rA] = b1.x; Bs[bf][kAo + 5][rA] = b1.y;               \
        Bs[bf][kAo + 6][rA] = b1.z; Bs[bf][kAo + 7][rA] = b1.w;               \
    }

    LOADG_O(0);
    STORES_O(0);
    __syncthreads();
    int buf = 0;
    for (int k0 = KT; k0 < Cn; k0 += KT) {
        LOADG_O(k0);
        mm16(As[buf], Bs[buf], acc, tx, ty);
        STORES_O(buf ^ 1);
        __syncthreads();
        buf ^= 1;
    }
    mm16(As[buf], Bs[buf], acc, tx, ty);

#pragma unroll
    for (int i = 0; i < 8; ++i)
        st_row(Ab + (size_t)(i0 + ty * 8 + i) * Nn + n0 + tx * 8, acc[i], 0.f);
}

// -------------------------------------------------------------------------
extern "C" void kernel_launch(void* const* d_in, const int* in_sizes, int n_in,
                              void* d_out, int out_size) {
    const float* x = (const float*)d_in[0];
    const float* Wf = (const float*)d_in[1];
    const float* bf = (const float*)d_in[2];
    const float* Wg = (const float*)d_in[3];
    const float* bg = (const float*)d_in[4];
    const float* Wh = (const float*)d_in[5];
    const float* bh = (const float*)d_in[6];
    const float* Wo = (const float*)d_in[7];
    const float* bo = (const float*)d_in[8];
    float* out = (float*)d_out;

    float *pF, *pG, *pH, *pA;
    cudaGetSymbolAddress((void**)&pF, g_F);
    cudaGetSymbolAddress((void**)&pG, g_G);
    cudaGetSymbolAddress((void**)&pH, g_H);
    cudaGetSymbolAddress((void**)&pA, g_attn);

    dim3 gconv(Nn / 128, Cn / 128, Bn);
    gemm_conv<<<gconv, 256>>>(Wf, bf, x, pF);
    gemm_conv<<<gconv, 256>>>(Wg, bg, x, pG);
    gemm_conv<<<gconv, 256>>>(Wh, bh, x, pH);
    gemm_s_kernel<<<dim3(Cn / 128, Cn / 128, Bn * SPLITS), 256>>>();
    softmax_kernel<<<Bn * Cn, 256>>>();
    gemm_out_kernel<<<dim3(Nn / 128, Cn / 128, Bn), 256>>>();
    gemm_conv<<<gconv, 256>>>(Wo, bo, pA, out);
}

// round 5
// speedup vs baseline: 2.1222x; 1.9221x over previous
#include <cuda_runtime.h>
#include <cuda_bf16.h>
#include <cstdint>
#include <cstddef>

typedef unsigned long long u64;
typedef __nv_bfloat16 bf16;

#define Bn 8
#define Cn 256
#define Nn 4096
#define SPLITS 8

// ---------------- device scratch (no allocations allowed) ----------------
__device__ bf16 g_XTh[Bn * Nn * Cn], g_XTl[Bn * Nn * Cn];  // x^T hi/lo [b][n][k]
__device__ bf16 g_Fh[Bn * Cn * Nn], g_Fl[Bn * Cn * Nn];    // conv outs [b][c][n]
__device__ bf16 g_Gh[Bn * Cn * Nn], g_Gl[Bn * Cn * Nn];
__device__ bf16 g_Hh[Bn * Cn * Nn], g_Hl[Bn * Cn * Nn];
__device__ bf16 g_FTh[Bn * Cn * Nn], g_FTl[Bn * Cn * Nn];  // FrT [b][c][n']
__device__ bf16 g_GTh[Bn * Cn * Nn], g_GTl[Bn * Cn * Nn];
__device__ bf16 g_aTh[Bn * Nn * Cn], g_aTl[Bn * Nn * Cn];  // attnT [b][n'][i]
__device__ float g_sPart[SPLITS * Bn * Cn * Cn];
__device__ float g_beta[Bn * Cn * Cn];

// ---------------- helpers -------------------------------------------------
#define SWZ(o) ((o) ^ (((o) >> 3) & 0x70))

__device__ __forceinline__ uint32_t s2u(const void* p) {
    uint32_t a;
    asm("{ .reg .u64 t; cvta.to.shared.u64 t, %1; cvt.u32.u64 %0, t; }"
        : "=r"(a) : "l"(p));
    return a;
}

__device__ __forceinline__ uint32_t splitpk_hi(float a, float b, uint32_t& lo) {
    bf16 h0 = __float2bfloat16(a), h1 = __float2bfloat16(b);
    bf16 l0 = __float2bfloat16(a - __bfloat162float(h0));
    bf16 l1 = __float2bfloat16(b - __bfloat162float(h1));
    lo = (uint32_t)__bfloat16_as_ushort(l0) |
         ((uint32_t)__bfloat16_as_ushort(l1) << 16);
    return (uint32_t)__bfloat16_as_ushort(h0) |
           ((uint32_t)__bfloat16_as_ushort(h1) << 16);
}

__device__ __forceinline__ void ldm4(uint32_t* r, uint32_t addr) {
    asm volatile(
        "ldmatrix.sync.aligned.m8n8.x4.shared.b16 {%0,%1,%2,%3}, [%4];"
        : "=r"(r[0]), "=r"(r[1]), "=r"(r[2]), "=r"(r[3]) : "r"(addr));
}
__device__ __forceinline__ void mma16816(float* c, const uint32_t* a,
                                         uint32_t b0, uint32_t b1) {
    asm volatile(
        "mma.sync.aligned.m16n8k16.row.col.f32.bf16.bf16.f32 "
        "{%0,%1,%2,%3}, {%4,%5,%6,%7}, {%8,%9}, {%0,%1,%2,%3};"
        : "+f"(c[0]), "+f"(c[1]), "+f"(c[2]), "+f"(c[3])
        : "r"(a[0]), "r"(a[1]), "r"(a[2]), "r"(a[3]), "r"(b0), "r"(b1));
}

// ---------------- generic HMMA GEMM ---------------------------------------
// D[m0:128][n0:128] = sum_k A[m][k]*B[n][k]; A,B K-major; hi/lo split x3 mma
template <bool AF32, bool BF32, bool OB16>
__global__ __launch_bounds__(256, 2)
void gemm_tc(const void* Ah_, const void* Al_, const void* Bh_, const void* Bl_,
             size_t sA, size_t sB, int K, int splits,
             size_t Abat, size_t Bbat, size_t Obat,
             const float* bias, void* Oh_, void* Ol_, size_t sO) {
    extern __shared__ __align__(128) char smem[];
    const int tid = threadIdx.x, lane = tid & 31, wid = tid >> 5;
    const int wm = wid >> 2, wn = wid & 3;  // 2x4 warp grid, 64x32 tiles
    const int z = blockIdx.z, b = z / splits, sp = z - b * splits;
    const int kb = sp * K;
    const int m0 = blockIdx.y * 128, n0 = blockIdx.x * 128;
    const uint32_t sb = s2u(smem);
    char* AHI = smem;
    char* ALO = smem + 16384;
    char* BHI = smem + 32768;
    char* BLO = smem + 49152;

    float acc[4][4][4] = {};

    const int lrow = tid >> 3;       // loader: base row 0..31
    const int lq = tid & 7;          // 16B unit within 64-elem row

    const int NS = K / 64;
    for (int s = 0; s < NS; ++s) {
        const int k0 = kb + s * 64;
        __syncthreads();
        // ---- load A tile (128 x 64)
        if constexpr (AF32) {
            const float* A = (const float*)Ah_ + Abat * b + (size_t)m0 * sA + k0;
#pragma unroll
            for (int i = 0; i < 4; ++i) {
                int r = lrow + 32 * i;
                const float* p = A + (size_t)r * sA + lq * 8;
                float4 v0 = *(const float4*)p, v1 = *(const float4*)(p + 4);
                float f[8] = {v0.x, v0.y, v0.z, v0.w, v1.x, v1.y, v1.z, v1.w};
                uint32_t hw[4], lw[4];
#pragma unroll
                for (int j = 0; j < 4; ++j)
                    hw[j] = splitpk_hi(f[2 * j], f[2 * j + 1], lw[j]);
                uint32_t o = SWZ(r * 128 + lq * 16);
                *(uint4*)(AHI + o) = make_uint4(hw[0], hw[1], hw[2], hw[3]);
                *(uint4*)(ALO + o) = make_uint4(lw[0], lw[1], lw[2], lw[3]);
            }
        } else {
            const bf16* A0 = (const bf16*)Ah_ + Abat * b + (size_t)m0 * sA + k0;
            const bf16* A1 = (const bf16*)Al_ + Abat * b + (size_t)m0 * sA + k0;
#pragma unroll
            for (int i = 0; i < 4; ++i) {
                int r = lrow + 32 * i;
                uint32_t o = SWZ(r * 128 + lq * 16);
                *(uint4*)(AHI + o) = *(const uint4*)(A0 + (size_t)r * sA + lq * 8);
                *(uint4*)(ALO + o) = *(const uint4*)(A1 + (size_t)r * sA + lq * 8);
            }
        }
        // ---- load B tile (128 x 64)
        if constexpr (BF32) {
            const float* B = (const float*)Bh_ + Bbat * b + (size_t)n0 * sB + k0;
#pragma unroll
            for (int i = 0; i < 4; ++i) {
                int r = lrow + 32 * i;
                const float* p = B + (size_t)r * sB + lq * 8;
                float4 v0 = *(const float4*)p, v1 = *(const float4*)(p + 4);
                float f[8] = {v0.x, v0.y, v0.z, v0.w, v1.x, v1.y, v1.z, v1.w};
                uint32_t hw[4], lw[4];
#pragma unroll
                for (int j = 0; j < 4; ++j)
                    hw[j] = splitpk_hi(f[2 * j], f[2 * j + 1], lw[j]);
                uint32_t o = SWZ(r * 128 + lq * 16);
                *(uint4*)(BHI + o) = make_uint4(hw[0], hw[1], hw[2], hw[3]);
                *(uint4*)(BLO + o) = make_uint4(lw[0], lw[1], lw[2], lw[3]);
            }
        } else {
            const bf16* B0 = (const bf16*)Bh_ + Bbat * b + (size_t)n0 * sB + k0;
            const bf16* B1 = (const bf16*)Bl_ + Bbat * b + (size_t)n0 * sB + k0;
#pragma unroll
            for (int i = 0; i < 4; ++i) {
                int r = lrow + 32 * i;
                uint32_t o = SWZ(r * 128 + lq * 16);
                *(uint4*)(BHI + o) = *(const uint4*)(B0 + (size_t)r * sB + lq * 8);
                *(uint4*)(BLO + o) = *(const uint4*)(B1 + (size_t)r * sB + lq * 8);
            }
        }
        __syncthreads();

        // ---- compute: 4 k16 steps
        const int trow = lane & 7, tsel = lane >> 3;
#pragma unroll
        for (int kk = 0; kk < 4; ++kk) {
            uint32_t aH[4][4], aL[4][4];
#pragma unroll
            for (int mt = 0; mt < 4; ++mt) {
                // tiles: (m0-7,k0)(m8-15,k0)(m0-7,k8)(m8-15,k8)
                int mr = wm * 64 + mt * 16 + (tsel & 1) * 8 + trow;
                int kby = kk * 32 + (tsel >> 1) * 16;
                uint32_t o = SWZ(mr * 128 + kby);
                ldm4(aH[mt], sb + o);
                ldm4(aL[mt], sb + 16384 + o);
            }
#pragma unroll
            for (int np = 0; np < 2; ++np) {
                // tiles: (n0-7,k0)(n0-7,k8)(n8-15,k0)(n8-15,k8)
                int nr = wn * 32 + np * 16 + (tsel >> 1) * 8 + trow;
                int kby = kk * 32 + (tsel & 1) * 16;
                uint32_t o = SWZ(nr * 128 + kby);
                uint32_t bH[4], bL[4];
                ldm4(bH, sb + 32768 + o);
                ldm4(bL, sb + 49152 + o);
#pragma unroll
                for (int mt = 0; mt < 4; ++mt)
#pragma unroll
                    for (int j = 0; j < 2; ++j) {
                        float* c = acc[mt][np * 2 + j];
                        mma16816(c, aH[mt], bH[2 * j], bH[2 * j + 1]);
                        mma16816(c, aH[mt], bL[2 * j], bL[2 * j + 1]);
                        mma16816(c, aL[mt], bH[2 * j], bH[2 * j + 1]);
                    }
            }
        }
    }

    // ---- epilogue
#pragma unroll
    for (int mt = 0; mt < 4; ++mt) {
        const int r0 = m0 + wm * 64 + mt * 16 + (lane >> 2);
        const float bz0 = bias ? bias[r0] : 0.f;
        const float bz1 = bias ? bias[r0 + 8] : 0.f;
#pragma unroll
        for (int nt = 0; nt < 4; ++nt) {
            const int col = n0 + wn * 32 + nt * 8 + 2 * (lane & 3);
            const float* c = acc[mt][nt];
            if constexpr (OB16) {
                bf16* oh = (bf16*)Oh_ + Obat * z;
                bf16* ol = (bf16*)Ol_ + Obat * z;
                uint32_t lo0, lo1;
                uint32_t hi0 = splitpk_hi(c[0] + bz0, c[1] + bz0, lo0);
                uint32_t hi1 = splitpk_hi(c[2] + bz1, c[3] + bz1, lo1);
                *(uint32_t*)(oh + (size_t)r0 * sO + col) = hi0;
                *(uint32_t*)(ol + (size_t)r0 * sO + col) = lo0;
                *(uint32_t*)(oh + (size_t)(r0 + 8) * sO + col) = hi1;
                *(uint32_t*)(ol + (size_t)(r0 + 8) * sO + col) = lo1;
            } else {
                float* o = (float*)Oh_ + Obat * z;
                *(float2*)(o + (size_t)r0 * sO + col) =
                    make_float2(c[0] + bz0, c[1] + bz0);
                *(float2*)(o + (size_t)(r0 + 8) * sO + col) =
                    make_float2(c[2] + bz1, c[3] + bz1);
            }
        }
    }
}

// ---------------- transpose x [b][k][n] -> XT [b][n][k] + hi/lo split -----
__global__ __launch_bounds__(256) void transpose_split_x(
    const float* __restrict__ x, bf16* __restrict__ xh, bf16* __restrict__ xl) {
    const int b = blockIdx.z, n0 = blockIdx.x * 64, k0 = blockIdx.y * 64;
    __shared__ float tt[64][65];
    const float* xb = x + ((size_t)b * Cn + k0) * Nn + n0;
    for (int c = threadIdx.x; c < 64 * 16; c += 256) {
        int r = c >> 4, q = c & 15;
        float4 v = *(const float4*)(xb + (size_t)r * Nn + q * 4);
        tt[q * 4 + 0][r] = v.x;
        tt[q * 4 + 1][r] = v.y;
        tt[q * 4 + 2][r] = v.z;
        tt[q * 4 + 3][r] = v.w;
    }
    __syncthreads();
    const size_t ob = ((size_t)b * Nn + n0) * Cn + k0;
    for (int c = threadIdx.x; c < 64 * 8; c += 256) {
        int r = c >> 3, q = c & 7;
        uint32_t hw[4], lw[4];
#pragma unroll
        for (int j = 0; j < 4; ++j)
            hw[j] = splitpk_hi(tt[r][q * 8 + 2 * j], tt[r][q * 8 + 2 * j + 1], lw[j]);
        *(uint4*)(xh + ob + (size_t)r * Cn + q * 8) =
            make_uint4(hw[0], hw[1], hw[2], hw[3]);
        *(uint4*)(xl + ob + (size_t)r * Cn + q * 8) =
            make_uint4(lw[0], lw[1], lw[2], lw[3]);
    }
}

// -------- transpose bf16 [4096][256]-view -> [256][4096], 4 tensors -------
__global__ __launch_bounds__(256) void transpose_bf16_k(
    const bf16* __restrict__ i0, const bf16* __restrict__ i1,
    const bf16* __restrict__ i2, const bf16* __restrict__ i3,
    bf16* __restrict__ o0, bf16* __restrict__ o1,
    bf16* __restrict__ o2, bf16* __restrict__ o3) {
    const int zz = blockIdx.z, t = zz >> 3, b = zz & 7;
    const bf16* in = t == 0 ? i0 : t == 1 ? i1 : t == 2 ? i2 : i3;
    bf16* out = t == 0 ? o0 : t == 1 ? o1 : t == 2 ? o2 : o3;
    const int n0 = blockIdx.x * 64, c0 = blockIdx.y * 64;
    __shared__ bf16 tt[64][72];
    const bf16* ib = in + ((size_t)b * Nn + n0) * Cn + c0;
    for (int c = threadIdx.x; c < 64 * 8; c += 256) {
        int r = c >> 3, q = c & 7;
        union { uint4 v; bf16 e[8]; } u;
        u.v = *(const uint4*)(ib + (size_t)r * Cn + q * 8);
#pragma unroll
        for (int j = 0; j < 8; ++j) tt[q * 8 + j][r] = u.e[j];
    }
    __syncthreads();
    bf16* ob = out + ((size_t)b * Cn + c0) * Nn + n0;
    for (int c = threadIdx.x; c < 64 * 8; c += 256) {
        int r = c >> 3, q = c & 7;
        *(uint4*)(ob + (size_t)r * Nn + q * 8) = *(const uint4*)&tt[r][q * 8];
    }
}

// ---------------- softmax over split-K partials ---------------------------
__global__ __launch_bounds__(256) void softmax_kernel() {
    const int row = blockIdx.x;  // b*Cn + i
    const int b = row >> 8, i = row & 255;
    const int j = threadIdx.x;
    float v = 0.f;
#pragma unroll
    for (int sp = 0; sp < SPLITS; ++sp)
        v += g_sPart[((size_t)(b * SPLITS + sp) << 16) + i * Cn + j];
    __shared__ float red[256];
    red[j] = v;
    __syncthreads();
    for (int s = 128; s > 0; s >>= 1) {
        if (j < s) red[j] = fmaxf(red[j], red[j + s]);
        __syncthreads();
    }
    const float mx = red[0];
    __syncthreads();
    const float e = expf(v - mx);
    red[j] = e;
    __syncthreads();
    for (int s = 128; s > 0; s >>= 1) {
        if (j < s) red[j] += red[j + s];
        __syncthreads();
    }
    g_beta[(size_t)row * Cn + j] = e / red[0];
}

// -------------------------------------------------------------------------
extern "C" void kernel_launch(void* const* d_in, const int* in_sizes, int n_in,
                              void* d_out, int out_size) {
    const float* x = (const float*)d_in[0];
    const float* Wf = (const float*)d_in[1];
    const float* bfp = (const float*)d_in[2];
    const float* Wg = (const float*)d_in[3];
    const float* bg = (const float*)d_in[4];
    const float* Wh = (const float*)d_in[5];
    const float* bh = (const float*)d_in[6];
    const float* Wo = (const float*)d_in[7];
    const float* bo = (const float*)d_in[8];
    float* out = (float*)d_out;

    bf16 *XTh, *XTl, *Fh, *Fl, *Gh, *Gl, *Hh, *Hl, *FTh, *FTl, *GTh, *GTl,
        *aTh, *aTl;
    float *sPart, *beta;
    cudaGetSymbolAddress((void**)&XTh, g_XTh);
    cudaGetSymbolAddress((void**)&XTl, g_XTl);
    cudaGetSymbolAddress((void**)&Fh, g_Fh);
    cudaGetSymbolAddress((void**)&Fl, g_Fl);
    cudaGetSymbolAddress((void**)&Gh, g_Gh);
    cudaGetSymbolAddress((void**)&Gl, g_Gl);
    cudaGetSymbolAddress((void**)&Hh, g_Hh);
    cudaGetSymbolAddress((void**)&Hl, g_Hl);
    cudaGetSymbolAddress((void**)&FTh, g_FTh);
    cudaGetSymbolAddress((void**)&FTl, g_FTl);
    cudaGetSymbolAddress((void**)&GTh, g_GTh);
    cudaGetSymbolAddress((void**)&GTl, g_GTl);
    cudaGetSymbolAddress((void**)&aTh, g_aTh);
    cudaGetSymbolAddress((void**)&aTl, g_aTl);
    cudaGetSymbolAddress((void**)&sPart, g_sPart);
    cudaGetSymbolAddress((void**)&beta, g_beta);

    const int SMSZ = 65536;
    cudaFuncSetAttribute(gemm_tc<true, false, true>,
                         cudaFuncAttributeMaxDynamicSharedMemorySize, SMSZ);
    cudaFuncSetAttribute(gemm_tc<false, false, false>,
                         cudaFuncAttributeMaxDynamicSharedMemorySize, SMSZ);
    cudaFuncSetAttribute(gemm_tc<false, true, true>,
                         cudaFuncAttributeMaxDynamicSharedMemorySize, SMSZ);
    cudaFuncSetAttribute(gemm_tc<true, false, false>,
                         cudaFuncAttributeMaxDynamicSharedMemorySize, SMSZ);

    const size_t CN = (size_t)Cn * Nn;  // 1048576

    // 1) x -> XT hi/lo
    transpose_split_x<<<dim3(Nn / 64, Cn / 64, Bn), 256>>>(x, XTh, XTl);

    // 2) conv F,G,H: D[o][n] = sum_k W[o][k] XT[n][k] -> bf16 hi/lo [o][n]
    dim3 gconv(Nn / 128, Cn / 128, Bn);
    gemm_tc<true, false, true><<<gconv, 256, SMSZ>>>(
        Wf, nullptr, XTh, XTl, Cn, Cn, Cn, 1, 0, CN, CN, bfp, Fh, Fl, Nn);
    gemm_tc<true, false, true><<<gconv, 256, SMSZ>>>(
        Wg, nullptr, XTh, XTl, Cn, Cn, Cn, 1, 0, CN, CN, bg, Gh, Gl, Nn);
    gemm_tc<true, false, true><<<gconv, 256, SMSZ>>>(
        Wh, nullptr, XTh, XTl, Cn, Cn, Cn, 1, 0, CN, CN, bh, Hh, Hl, Nn);

    // 3) transpose F,G (hi & lo) -> FrT/GrT [c][n']
    transpose_bf16_k<<<dim3(Nn / 64, Cn / 64, 4 * Bn), 256>>>(
        Fh, Fl, Gh, Gl, FTh, FTl, GTh, GTl);

    // 4) s partials: D[i][j] = sum_n GT[i][n] FT[j][n], split-K=8
    gemm_tc<false, false, false><<<dim3(2, 2, Bn * SPLITS), 256, SMSZ>>>(
        GTh, GTl, FTh, FTl, Nn, Nn, Nn / SPLITS, SPLITS, CN, CN,
        (size_t)Cn * Cn, nullptr, sPart, nullptr, Cn);

    // 5) softmax
    softmax_kernel<<<Bn * Cn, 256>>>();

    // 6) attnT[p][i] = sum_j Hbuf[p][j] beta[i][j]
    gemm_tc<false, true, true><<<dim3(Cn / 128, Nn / 128, Bn), 256, SMSZ>>>(
        Hh, Hl, beta, nullptr, Cn, Cn, Cn, 1, CN, (size_t)Cn * Cn, CN,
        nullptr, aTh, aTl, Cn);

    // 7) final conv: y[o][p] = sum_i Wo[o][i] attnT[p][i] -> d_out fp32
    gemm_tc<true, false, false><<<gconv, 256, SMSZ>>>(
        Wo, nullptr, aTh, aTl, Cn, Cn, Cn, 1, 0, CN, CN, bo, out, nullptr, Nn);
}

// round 6
// speedup vs baseline: 2.3153x; 1.0910x over previous
#include <cuda_runtime.h>
#include <cuda_bf16.h>
#include <cstdint>
#include <cstddef>

typedef unsigned long long u64;
typedef __nv_bfloat16 bf16;

#define Bn 8
#define Cn 256
#define Nn 4096
#define SPLITS 8
#define CN ((size_t)Cn * Nn)

// ---------------- device scratch (no allocations allowed) ----------------
__device__ bf16 g_XTh[Bn * Nn * Cn], g_XTl[Bn * Nn * Cn];   // x^T hi/lo [b][n][k]
__device__ bf16 g_FGHh[Bn * 3 * Cn * Nn], g_FGHl[Bn * 3 * Cn * Nn];
__device__ bf16 g_FTh[Bn * Cn * Nn], g_FTl[Bn * Cn * Nn];   // FrT [b][c][n']
__device__ bf16 g_GTh[Bn * Cn * Nn], g_GTl[Bn * Cn * Nn];
__device__ bf16 g_aTh[Bn * Nn * Cn], g_aTl[Bn * Nn * Cn];   // attnT [b][n'][i]
__device__ bf16 g_Wsh[4 * Cn * Cn], g_Wsl[4 * Cn * Cn];     // stacked weights
__device__ float g_bstk[3 * Cn];
__device__ float g_sPart[SPLITS * Bn * Cn * Cn];
__device__ bf16 g_betah[Bn * Cn * Cn], g_betal[Bn * Cn * Cn];

// ---------------- helpers -------------------------------------------------
#define SWZ(o) ((o) ^ (((o) >> 3) & 0x70))

__device__ __forceinline__ uint32_t s2u(const void* p) {
    uint32_t a;
    asm("{ .reg .u64 t; cvta.to.shared.u64 t, %1; cvt.u32.u64 %0, t; }"
        : "=r"(a) : "l"(p));
    return a;
}
__device__ __forceinline__ uint32_t splitpk_hi(float a, float b, uint32_t& lo) {
    bf16 h0 = __float2bfloat16(a), h1 = __float2bfloat16(b);
    bf16 l0 = __float2bfloat16(a - __bfloat162float(h0));
    bf16 l1 = __float2bfloat16(b - __bfloat162float(h1));
    lo = (uint32_t)__bfloat16_as_ushort(l0) |
         ((uint32_t)__bfloat16_as_ushort(l1) << 16);
    return (uint32_t)__bfloat16_as_ushort(h0) |
           ((uint32_t)__bfloat16_as_ushort(h1) << 16);
}
__device__ __forceinline__ void ldm4(uint32_t* r, uint32_t addr) {
    asm volatile(
        "ldmatrix.sync.aligned.m8n8.x4.shared.b16 {%0,%1,%2,%3}, [%4];"
        : "=r"(r[0]), "=r"(r[1]), "=r"(r[2]), "=r"(r[3]) : "r"(addr));
}
__device__ __forceinline__ void mma16816(float* c, const uint32_t* a,
                                         uint32_t b0, uint32_t b1) {
    asm volatile(
        "mma.sync.aligned.m16n8k16.row.col.f32.bf16.bf16.f32 "
        "{%0,%1,%2,%3}, {%4,%5,%6,%7}, {%8,%9}, {%0,%1,%2,%3};"
        : "+f"(c[0]), "+f"(c[1]), "+f"(c[2]), "+f"(c[3])
        : "r"(a[0]), "r"(a[1]), "r"(a[2]), "r"(a[3]), "r"(b0), "r"(b1));
}
__device__ __forceinline__ void cpa16(uint32_t dst, const void* src) {
    asm volatile("cp.async.cg.shared.global [%0], [%1], 16;"
                 :: "r"(dst), "l"(src) : "memory");
}

// ---------------- HMMA GEMM, all-bf16, cp.async double-buffered -----------
// D[m0:128][n0:128] = sum_k A[m][k]*B[n][k]; hi/lo split, 3-mma emulation
template <bool OB16>
__global__ __launch_bounds__(256, 1)
void gemm_bf(const bf16* __restrict__ Ah, const bf16* __restrict__ Al,
             const bf16* __restrict__ Bh, const bf16* __restrict__ Bl,
             size_t sA, size_t sB, int K, int splits,
             size_t Abat, size_t Bbat, size_t Obat,
             const float* __restrict__ bias, void* Oh_, void* Ol_, size_t sO) {
    extern __shared__ __align__(128) char smem[];
    const int tid = threadIdx.x, lane = tid & 31, wid = tid >> 5;
    const int wm = wid >> 2, wn = wid & 3;  // 2x4 warp grid, 64x32 tiles
    const int z = blockIdx.z, b = z / splits, sp = z - b * splits;
    const int kb = sp * K;
    const int m0 = blockIdx.y * 128, n0 = blockIdx.x * 128;
    const uint32_t sb = s2u(smem);

    const bf16* A0 = Ah + Abat * b + (size_t)m0 * sA + kb;
    const bf16* A1 = Al + Abat * b + (size_t)m0 * sA + kb;
    const bf16* B0 = Bh + Bbat * b + (size_t)n0 * sB + kb;
    const bf16* B1 = Bl + Bbat * b + (size_t)n0 * sB + kb;

    const int lrow = tid >> 3, lq = tid & 7;

#define LOAD_SLAB(s, stg)                                                     \
    {                                                                         \
        const uint32_t bb = sb + (stg) * 65536;                               \
        const int k0 = (s) * 64;                                              \
        _Pragma("unroll") for (int i = 0; i < 4; ++i) {                       \
            int r = lrow + 32 * i;                                            \
            uint32_t o = SWZ(r * 128 + lq * 16);                              \
            cpa16(bb + o, A0 + (size_t)r * sA + k0 + lq * 8);                 \
            cpa16(bb + 16384 + o, A1 + (size_t)r * sA + k0 + lq * 8);         \
            cpa16(bb + 32768 + o, B0 + (size_t)r * sB + k0 + lq * 8);         \
            cpa16(bb + 49152 + o, B1 + (size_t)r * sB + k0 + lq * 8);         \
        }                                                                     \
        asm volatile("cp.async.commit_group;" ::: "memory");                  \
    }

    float acc[4][4][4] = {};
    const int NS = K / 64;
    LOAD_SLAB(0, 0);

    for (int s = 0; s < NS; ++s) {
        const int stg = s & 1;
        if (s + 1 < NS) {
            LOAD_SLAB(s + 1, stg ^ 1);
            asm volatile("cp.async.wait_group 1;" ::: "memory");
        } else {
            asm volatile("cp.async.wait_group 0;" ::: "memory");
        }
        __syncthreads();

        const uint32_t base = sb + stg * 65536;
        const int trow = lane & 7, tsel = lane >> 3;
#pragma unroll
        for (int kk = 0; kk < 4; ++kk) {
            uint32_t aH[4][4], aL[4][4];
#pragma unroll
            for (int mt = 0; mt < 4; ++mt) {
                int mr = wm * 64 + mt * 16 + (tsel & 1) * 8 + trow;
                int kby = kk * 32 + (tsel >> 1) * 16;
                uint32_t o = SWZ(mr * 128 + kby);
                ldm4(aH[mt], base + o);
                ldm4(aL[mt], base + 16384 + o);
            }
#pragma unroll
            for (int np = 0; np < 2; ++np) {
                int nr = wn * 32 + np * 16 + (tsel >> 1) * 8 + trow;
                int kby = kk * 32 + (tsel & 1) * 16;
                uint32_t o = SWZ(nr * 128 + kby);
                uint32_t bH[4], bL[4];
                ldm4(bH, base + 32768 + o);
                ldm4(bL, base + 49152 + o);
#pragma unroll
                for (int mt = 0; mt < 4; ++mt)
#pragma unroll
                    for (int j = 0; j < 2; ++j) {
                        float* c = acc[mt][np * 2 + j];
                        mma16816(c, aH[mt], bH[2 * j], bH[2 * j + 1]);
                        mma16816(c, aH[mt], bL[2 * j], bL[2 * j + 1]);
                        mma16816(c, aL[mt], bH[2 * j], bH[2 * j + 1]);
                    }
            }
        }
        __syncthreads();
    }

    // ---- epilogue
#pragma unroll
    for (int mt = 0; mt < 4; ++mt) {
        const int r0 = m0 + wm * 64 + mt * 16 + (lane >> 2);
        const float bz0 = bias ? bias[r0] : 0.f;
        const float bz1 = bias ? bias[r0 + 8] : 0.f;
#pragma unroll
        for (int nt = 0; nt < 4; ++nt) {
            const int col = n0 + wn * 32 + nt * 8 + 2 * (lane & 3);
            const float* c = acc[mt][nt];
            if constexpr (OB16) {
                bf16* oh = (bf16*)Oh_ + Obat * z;
                bf16* ol = (bf16*)Ol_ + Obat * z;
                uint32_t lo0, lo1;
                uint32_t hi0 = splitpk_hi(c[0] + bz0, c[1] + bz0, lo0);
                uint32_t hi1 = splitpk_hi(c[2] + bz1, c[3] + bz1, lo1);
                *(uint32_t*)(oh + (size_t)r0 * sO + col) = hi0;
                *(uint32_t*)(ol + (size_t)r0 * sO + col) = lo0;
                *(uint32_t*)(oh + (size_t)(r0 + 8) * sO + col) = hi1;
                *(uint32_t*)(ol + (size_t)(r0 + 8) * sO + col) = lo1;
            } else {
                float* o = (float*)Oh_ + Obat * z;
                *(float2*)(o + (size_t)r0 * sO + col) =
                    make_float2(c[0] + bz0, c[1] + bz0);
                *(float2*)(o + (size_t)(r0 + 8) * sO + col) =
                    make_float2(c[2] + bz1, c[3] + bz1);
            }
        }
    }
}

// ---------------- prep: split 4 weight matrices + stack biases ------------
__global__ __launch_bounds__(256) void prep_weights(
    const float* __restrict__ Wf, const float* __restrict__ Wg,
    const float* __restrict__ Wh, const float* __restrict__ Wo,
    const float* __restrict__ b0, const float* __restrict__ b1,
    const float* __restrict__ b2) {
    int idx = blockIdx.x * 256 + threadIdx.x;  // pair index, 4*32768 total
    const float* W = (idx >> 15) == 0 ? Wf
                     : (idx >> 15) == 1 ? Wg
                     : (idx >> 15) == 2 ? Wh : Wo;
    int p = idx & 32767;
    uint32_t lo, hi = splitpk_hi(W[2 * p], W[2 * p + 1], lo);
    ((uint32_t*)g_Wsh)[idx] = hi;
    ((uint32_t*)g_Wsl)[idx] = lo;
    if (blockIdx.x == 0) {
        g_bstk[threadIdx.x] = b0[threadIdx.x];
        g_bstk[256 + threadIdx.x] = b1[threadIdx.x];
        g_bstk[512 + threadIdx.x] = b2[threadIdx.x];
    }
}

// ---------------- transpose x [b][k][n] -> XT [b][n][k] + hi/lo split -----
__global__ __launch_bounds__(256) void transpose_split_x(
    const float* __restrict__ x, bf16* __restrict__ xh, bf16* __restrict__ xl) {
    const int b = blockIdx.z, n0 = blockIdx.x * 64, k0 = blockIdx.y * 64;
    __shared__ float tt[64][65];
    const float* xb = x + ((size_t)b * Cn + k0) * Nn + n0;
    for (int c = threadIdx.x; c < 64 * 16; c += 256) {
        int r = c >> 4, q = c & 15;
        float4 v = *(const float4*)(xb + (size_t)r * Nn + q * 4);
        tt[q * 4 + 0][r] = v.x;
        tt[q * 4 + 1][r] = v.y;
        tt[q * 4 + 2][r] = v.z;
        tt[q * 4 + 3][r] = v.w;
    }
    __syncthreads();
    const size_t ob = ((size_t)b * Nn + n0) * Cn + k0;
    for (int c = threadIdx.x; c < 64 * 8; c += 256) {
        int r = c >> 3, q = c & 7;
        uint32_t hw[4], lw[4];
#pragma unroll
        for (int j = 0; j < 4; ++j)
            hw[j] = splitpk_hi(tt[r][q * 8 + 2 * j], tt[r][q * 8 + 2 * j + 1], lw[j]);
        *(uint4*)(xh + ob + (size_t)r * Cn + q * 8) =
            make_uint4(hw[0], hw[1], hw[2], hw[3]);
        *(uint4*)(xl + ob + (size_t)r * Cn + q * 8) =
            make_uint4(lw[0], lw[1], lw[2], lw[3]);
    }
}

// -------- transpose Fr/Gr views ([4096][256]) -> FT/GT ([256][4096]) ------
__global__ __launch_bounds__(256) void transpose_fg() {
    const int zz = blockIdx.z, t = zz >> 3, b = zz & 7;
    const bf16* in = (t == 0   ? g_FGHh
                      : t == 1 ? g_FGHl
                      : t == 2 ? g_FGHh
                               : g_FGHl) +
                     (size_t)b * 3 * CN + (t >= 2 ? CN : 0);
    bf16* out = (t == 0   ? g_FTh
                 : t == 1 ? g_FTl
                 : t == 2 ? g_GTh
                          : g_GTl) +
                (size_t)b * CN;
    const int n0 = blockIdx.x * 64, c0 = blockIdx.y * 64;
    __shared__ bf16 tt[64][72];
    const bf16* ib = in + (size_t)n0 * Cn + c0;
    for (int c = threadIdx.x; c < 64 * 8; c += 256) {
        int r = c >> 3, q = c & 7;
        union { uint4 v; bf16 e[8]; } u;
        u.v = *(const uint4*)(ib + (size_t)r * Cn + q * 8);
#pragma unroll
        for (int j = 0; j < 8; ++j) tt[q * 8 + j][r] = u.e[j];
    }
    __syncthreads();
    bf16* ob = out + (size_t)c0 * Nn + n0;
    for (int c = threadIdx.x; c < 64 * 8; c += 256) {
        int r = c >> 3, q = c & 7;
        *(uint4*)(ob + (size_t)r * Nn + q * 8) = *(const uint4*)&tt[r][q * 8];
    }
}

// ---------------- softmax over split-K partials -> bf16 hi/lo beta --------
__global__ __launch_bounds__(256) void softmax_kernel() {
    const int row = blockIdx.x;  // b*Cn + i
    const int b = row >> 8, i = row & 255;
    const int j = threadIdx.x;
    float v = 0.f;
#pragma unroll
    for (int sp = 0; sp < SPLITS; ++sp)
        v += g_sPart[((size_t)(b * SPLITS + sp) << 16) + i * Cn + j];
    __shared__ float red[256];
    red[j] = v;
    __syncthreads();
    for (int s = 128; s > 0; s >>= 1) {
        if (j < s) red[j] = fmaxf(red[j], red[j + s]);
        __syncthreads();
    }
    const float mx = red[0];
    __syncthreads();
    const float e = expf(v - mx);
    red[j] = e;
    __syncthreads();
    for (int s = 128; s > 0; s >>= 1) {
        if (j < s) red[j] += red[j + s];
        __syncthreads();
    }
    const float r = e / red[0];
    bf16 h = __float2bfloat16(r);
    bf16 l = __float2bfloat16(r - __bfloat162float(h));
    g_betah[(size_t)row * Cn + j] = h;
    g_betal[(size_t)row * Cn + j] = l;
}

// -------------------------------------------------------------------------
extern "C" void kernel_launch(void* const* d_in, const int* in_sizes, int n_in,
                              void* d_out, int out_size) {
    const float* x = (const float*)d_in[0];
    const float* Wf = (const float*)d_in[1];
    const float* bfp = (const float*)d_in[2];
    const float* Wg = (const float*)d_in[3];
    const float* bg = (const float*)d_in[4];
    const float* Wh = (const float*)d_in[5];
    const float* bh = (const float*)d_in[6];
    const float* Wo = (const float*)d_in[7];
    const float* bo = (const float*)d_in[8];
    float* out = (float*)d_out;

    bf16 *XTh, *XTl, *FGHh, *FGHl, *FTh, *FTl, *GTh, *GTl, *aTh, *aTl, *Wsh,
        *Wsl, *betah, *betal;
    float *sPart, *bstk;
    cudaGetSymbolAddress((void**)&XTh, g_XTh);
    cudaGetSymbolAddress((void**)&XTl, g_XTl);
    cudaGetSymbolAddress((void**)&FGHh, g_FGHh);
    cudaGetSymbolAddress((void**)&FGHl, g_FGHl);
    cudaGetSymbolAddress((void**)&FTh, g_FTh);
    cudaGetSymbolAddress((void**)&FTl, g_FTl);
    cudaGetSymbolAddress((void**)&GTh, g_GTh);
    cudaGetSymbolAddress((void**)&GTl, g_GTl);
    cudaGetSymbolAddress((void**)&aTh, g_aTh);
    cudaGetSymbolAddress((void**)&aTl, g_aTl);
    cudaGetSymbolAddress((void**)&Wsh, g_Wsh);
    cudaGetSymbolAddress((void**)&Wsl, g_Wsl);
    cudaGetSymbolAddress((void**)&betah, g_betah);
    cudaGetSymbolAddress((void**)&betal, g_betal);
    cudaGetSymbolAddress((void**)&sPart, g_sPart);
    cudaGetSymbolAddress((void**)&bstk, g_bstk);

    const int SMSZ = 131072;
    cudaFuncSetAttribute(gemm_bf<true>,
                         cudaFuncAttributeMaxDynamicSharedMemorySize, SMSZ);
    cudaFuncSetAttribute(gemm_bf<false>,
                         cudaFuncAttributeMaxDynamicSharedMemorySize, SMSZ);

    // 0) weights -> bf16 hi/lo (stacked), biases -> stacked
    prep_weights<<<512, 256>>>(Wf, Wg, Wh, Wo, bfp, bg, bh);

    // 1) x -> XT hi/lo
    transpose_split_x<<<dim3(Nn / 64, Cn / 64, Bn), 256>>>(x, XTh, XTl);

    // 2) merged conv F,G,H: D[m][n] = sum_k Wstk[m][k] XT[n][k], m in 0..767
    gemm_bf<true><<<dim3(Nn / 128, 6, Bn), 256, SMSZ>>>(
        Wsh, Wsl, XTh, XTl, Cn, Cn, Cn, 1, 0, CN, 3 * CN, bstk,
        FGHh, FGHl, Nn);

    // 3) transpose Fr, Gr -> FT, GT
    transpose_fg<<<dim3(Nn / 64, Cn / 64, 4 * Bn), 256>>>();

    // 4) s partials: D[i][j] = sum_n GT[i][n] FT[j][n], split-K=8 -> fp32
    gemm_bf<false><<<dim3(2, 2, Bn * SPLITS), 256, SMSZ>>>(
        GTh, GTl, FTh, FTl, Nn, Nn, Nn / SPLITS, SPLITS, CN, CN,
        (size_t)Cn * Cn, nullptr, sPart, nullptr, Cn);

    // 5) softmax -> beta bf16 hi/lo
    softmax_kernel<<<Bn * Cn, 256>>>();

    // 6) attnT[p][i] = sum_j Hr[p][j] beta[i][j]  (Hr = raw view of H part)
    gemm_bf<true><<<dim3(Cn / 128, Nn / 128, Bn), 256, SMSZ>>>(
        FGHh + 2 * CN, FGHl + 2 * CN, betah, betal, Cn, Cn, Cn, 1,
        3 * CN, (size_t)Cn * Cn, CN, nullptr, aTh, aTl, Cn);

    // 7) final conv: y[o][p] = sum_i Wo[o][i] attnT[p][i] -> d_out fp32
    gemm_bf<false><<<dim3(Nn / 128, Cn / 128, Bn), 256, SMSZ>>>(
        Wsh + 3 * (size_t)Cn * Cn, Wsl + 3 * (size_t)Cn * Cn, aTh, aTl,
        Cn, Cn, Cn, 1, 0, CN, CN, bo, out, nullptr, Nn);
}

// round 8
// speedup vs baseline: 2.6153x; 1.1295x over previous
#include <cuda_runtime.h>
#include <cuda_bf16.h>
#include <cstdint>
#include <cstddef>

typedef unsigned long long u64;
typedef __nv_bfloat16 bf16;

#define Bn 8
#define Cn 256
#define Nn 4096
#define SPLITS 8
#define CN ((size_t)Cn * Nn)

// ---------------- device scratch (no allocations allowed) ----------------
__device__ bf16 g_Xh[Bn * Cn * Nn], g_Xl[Bn * Cn * Nn];     // x hi/lo [b][c][n]
__device__ bf16 g_FGHh[Bn * 3 * Cn * Nn], g_FGHl[Bn * 3 * Cn * Nn];
__device__ bf16 g_aTh[Bn * Nn * Cn], g_aTl[Bn * Nn * Cn];   // attnT [b][n'][i]
__device__ bf16 g_Wsh[4 * Cn * Cn], g_Wsl[4 * Cn * Cn];     // stacked weights
__device__ float g_bstk[3 * Cn];
__device__ float g_sPart[SPLITS * Bn * Cn * Cn];
__device__ bf16 g_betah[Bn * Cn * Cn], g_betal[Bn * Cn * Cn];

// ---------------- helpers -------------------------------------------------
#define SWZ(o) ((o) ^ (((o) >> 3) & 0x70))

__device__ __forceinline__ uint32_t s2u(const void* p) {
    uint32_t a;
    asm("{ .reg .u64 t; cvta.to.shared.u64 t, %1; cvt.u32.u64 %0, t; }"
        : "=r"(a) : "l"(p));
    return a;
}
__device__ __forceinline__ uint32_t splitpk_hi(float a, float b, uint32_t& lo) {
    bf16 h0 = __float2bfloat16(a), h1 = __float2bfloat16(b);
    bf16 l0 = __float2bfloat16(a - __bfloat162float(h0));
    bf16 l1 = __float2bfloat16(b - __bfloat162float(h1));
    lo = (uint32_t)__bfloat16_as_ushort(l0) |
         ((uint32_t)__bfloat16_as_ushort(l1) << 16);
    return (uint32_t)__bfloat16_as_ushort(h0) |
           ((uint32_t)__bfloat16_as_ushort(h1) << 16);
}
__device__ __forceinline__ void ldm4(uint32_t* r, uint32_t addr) {
    asm volatile(
        "ldmatrix.sync.aligned.m8n8.x4.shared.b16 {%0,%1,%2,%3}, [%4];"
        : "=r"(r[0]), "=r"(r[1]), "=r"(r[2]), "=r"(r[3]) : "r"(addr));
}
__device__ __forceinline__ void ldm4t(uint32_t* r, uint32_t addr) {
    asm volatile(
        "ldmatrix.sync.aligned.m8n8.x4.trans.shared.b16 {%0,%1,%2,%3}, [%4];"
        : "=r"(r[0]), "=r"(r[1]), "=r"(r[2]), "=r"(r[3]) : "r"(addr));
}
__device__ __forceinline__ void mma16816(float* c, const uint32_t* a,
                                         uint32_t b0, uint32_t b1) {
    asm volatile(
        "mma.sync.aligned.m16n8k16.row.col.f32.bf16.bf16.f32 "
        "{%0,%1,%2,%3}, {%4,%5,%6,%7}, {%8,%9}, {%0,%1,%2,%3};"
        : "+f"(c[0]), "+f"(c[1]), "+f"(c[2]), "+f"(c[3])
        : "r"(a[0]), "r"(a[1]), "r"(a[2]), "r"(a[3]), "r"(b0), "r"(b1));
}
__device__ __forceinline__ void cpa16(uint32_t dst, const void* src) {
    asm volatile("cp.async.cg.shared.global [%0], [%1], 16;"
                 :: "r"(dst), "l"(src) : "memory");
}

// ---------------- HMMA GEMM, all-bf16, cp.async double-buffered -----------
// D[m0:128][n0:128] = sum_k A[m][k]*B[n][k]; hi/lo split, 3-mma emulation
// TR operands are stored MN-major in gmem ([k][col]); loaded via ldmatrix.trans
template <bool AT, bool BT, bool OB16>
__global__ __launch_bounds__(256, 1)
void gemm_bf(const bf16* __restrict__ Ah, const bf16* __restrict__ Al,
             const bf16* __restrict__ Bh, const bf16* __restrict__ Bl,
             size_t sA, size_t sB, int K, int splits,
             size_t Abat, size_t Bbat, size_t Obat,
             const float* __restrict__ bias, void* Oh_, void* Ol_, size_t sO) {
    extern __shared__ __align__(128) char smem[];
    const int tid = threadIdx.x, lane = tid & 31, wid = tid >> 5;
    const int wm = wid >> 2, wn = wid & 3;  // 2x4 warp grid, 64x32 tiles
    const int z = blockIdx.z, b = z / splits, sp = z - b * splits;
    const int kb = sp * K;
    const int m0 = blockIdx.y * 128, n0 = blockIdx.x * 128;
    const uint32_t sb = s2u(smem);

    // operand base pointers per mode
    const bf16* A0 = AT ? (Ah + Abat * b + (size_t)kb * sA + m0)
                        : (Ah + Abat * b + (size_t)m0 * sA + kb);
    const bf16* A1 = AT ? (Al + Abat * b + (size_t)kb * sA + m0)
                        : (Al + Abat * b + (size_t)m0 * sA + kb);
    const bf16* B0 = BT ? (Bh + Bbat * b + (size_t)kb * sB + n0)
                        : (Bh + Bbat * b + (size_t)n0 * sB + kb);
    const bf16* B1 = BT ? (Bl + Bbat * b + (size_t)kb * sB + n0)
                        : (Bl + Bbat * b + (size_t)n0 * sB + kb);

#define LOAD_OP(TR, off, Phi, Plo, stride, s)                                 \
    if constexpr (TR) {                                                       \
        _Pragma("unroll") for (int i = 0; i < 4; ++i) {                       \
            int ch = tid + 256 * i, kr = ch >> 4, cq = ch & 15;               \
            uint32_t o = (cq >> 3) * 8192 + SWZ(kr * 128 + (cq & 7) * 16);    \
            const size_t go = (size_t)((s) * 64 + kr) * (stride) + cq * 8;    \
            cpa16(bb + (off) + o, (Phi) + go);                                \
            cpa16(bb + (off) + 16384 + o, (Plo) + go);                        \
        }                                                                     \
    } else {                                                                  \
        _Pragma("unroll") for (int i = 0; i < 4; ++i) {                       \
            int r = (tid >> 3) + 32 * i, cq = tid & 7;                        \
            uint32_t o = SWZ(r * 128 + cq * 16);                              \
            const size_t go = (size_t)r * (stride) + (s) * 64 + cq * 8;       \
            cpa16(bb + (off) + o, (Phi) + go);                                \
            cpa16(bb + (off) + 16384 + o, (Plo) + go);                        \
        }                                                                     \
    }

#define LOAD_SLAB(s, stg)                                                     \
    {                                                                         \
        const uint32_t bb = sb + (stg) * 65536;                               \
        LOAD_OP(AT, 0, A0, A1, sA, s);                                        \
        LOAD_OP(BT, 32768, B0, B1, sB, s);                                    \
        asm volatile("cp.async.commit_group;" ::: "memory");                  \
    }

    float acc[4][4][4] = {};
    const int NS = K / 64;
    LOAD_SLAB(0, 0);

    for (int s = 0; s < NS; ++s) {
        const int stg = s & 1;
        if (s + 1 < NS) {
            LOAD_SLAB(s + 1, stg ^ 1);
            asm volatile("cp.async.wait_group 1;" ::: "memory");
        } else {
            asm volatile("cp.async.wait_group 0;" ::: "memory");
        }
        __syncthreads();

        const uint32_t base = sb + stg * 65536;
        const int trow = lane & 7, tsel = lane >> 3;
#pragma unroll
        for (int kk = 0; kk < 4; ++kk) {
            uint32_t aH[4][4], aL[4][4];
#pragma unroll
            for (int mt = 0; mt < 4; ++mt) {
                uint32_t o;
                if constexpr (AT) {
                    int krow = kk * 16 + (tsel >> 1) * 8 + trow;
                    int mcol = wm * 64 + mt * 16 + (tsel & 1) * 8;
                    o = (mcol >> 6) * 8192 + SWZ(krow * 128 + (mcol & 63) * 2);
                    ldm4t(aH[mt], base + o);
                    ldm4t(aL[mt], base + 16384 + o);
                } else {
                    int mr = wm * 64 + mt * 16 + (tsel & 1) * 8 + trow;
                    int kby = kk * 32 + (tsel >> 1) * 16;
                    o = SWZ(mr * 128 + kby);
                    ldm4(aH[mt], base + o);
                    ldm4(aL[mt], base + 16384 + o);
                }
            }
#pragma unroll
            for (int np = 0; np < 2; ++np) {
                uint32_t bH[4], bL[4];
                uint32_t o;
                if constexpr (BT) {
                    int krow = kk * 16 + (tsel & 1) * 8 + trow;
                    int ncol = wn * 32 + np * 16 + (tsel >> 1) * 8;
                    o = (ncol >> 6) * 8192 + SWZ(krow * 128 + (ncol & 63) * 2);
                    ldm4t(bH, base + 32768 + o);
                    ldm4t(bL, base + 49152 + o);
                } else {
                    int nr = wn * 32 + np * 16 + (tsel >> 1) * 8 + trow;
                    int kby = kk * 32 + (tsel & 1) * 16;
                    o = SWZ(nr * 128 + kby);
                    ldm4(bH, base + 32768 + o);
                    ldm4(bL, base + 49152 + o);
                }
#pragma unroll
                for (int mt = 0; mt < 4; ++mt)
#pragma unroll
                    for (int j = 0; j < 2; ++j) {
                        float* c = acc[mt][np * 2 + j];
                        mma16816(c, aH[mt], bH[2 * j], bH[2 * j + 1]);
                        mma16816(c, aH[mt], bL[2 * j], bL[2 * j + 1]);
                        mma16816(c, aL[mt], bH[2 * j], bH[2 * j + 1]);
                    }
            }
        }
        __syncthreads();
    }

    // ---- epilogue
#pragma unroll
    for (int mt = 0; mt < 4; ++mt) {
        const int r0 = m0 + wm * 64 + mt * 16 + (lane >> 2);
        const float bz0 = bias ? bias[r0] : 0.f;
        const float bz1 = bias ? bias[r0 + 8] : 0.f;
#pragma unroll
        for (int nt = 0; nt < 4; ++nt) {
            const int col = n0 + wn * 32 + nt * 8 + 2 * (lane & 3);
            const float* c = acc[mt][nt];
            if constexpr (OB16) {
                bf16* oh = (bf16*)Oh_ + Obat * z;
                bf16* ol = (bf16*)Ol_ + Obat * z;
                uint32_t lo0, lo1;
                uint32_t hi0 = splitpk_hi(c[0] + bz0, c[1] + bz0, lo0);
                uint32_t hi1 = splitpk_hi(c[2] + bz1, c[3] + bz1, lo1);
                *(uint32_t*)(oh + (size_t)r0 * sO + col) = hi0;
                *(uint32_t*)(ol + (size_t)r0 * sO + col) = lo0;
                *(uint32_t*)(oh + (size_t)(r0 + 8) * sO + col) = hi1;
                *(uint32_t*)(ol + (size_t)(r0 + 8) * sO + col) = lo1;
            } else {
                float* o = (float*)Oh_ + Obat * z;
                *(float2*)(o + (size_t)r0 * sO + col) =
                    make_float2(c[0] + bz0, c[1] + bz0);
                *(float2*)(o + (size_t)(r0 + 8) * sO + col) =
                    make_float2(c[2] + bz1, c[3] + bz1);
            }
        }
    }
}

// ---------------- prep: split 4 weight matrices + stack biases ------------
__global__ __launch_bounds__(256) void prep_weights(
    const float* __restrict__ Wf, const float* __restrict__ Wg,
    const float* __restrict__ Wh, const float* __restrict__ Wo,
    const float* __restrict__ b0, const float* __restrict__ b1,
    const float* __restrict__ b2) {
    int idx = blockIdx.x * 256 + threadIdx.x;  // pair index, 4*32768 total
    const float* W = (idx >> 15) == 0 ? Wf
                     : (idx >> 15) == 1 ? Wg
                     : (idx >> 15) == 2 ? Wh : Wo;
    int p = idx & 32767;
    uint32_t lo, hi = splitpk_hi(W[2 * p], W[2 * p + 1], lo);
    ((uint32_t*)g_Wsh)[idx] = hi;
    ((uint32_t*)g_Wsl)[idx] = lo;
    if (blockIdx.x == 0) {
        g_bstk[threadIdx.x] = b0[threadIdx.x];
        g_bstk[256 + threadIdx.x] = b1[threadIdx.x];
        g_bstk[512 + threadIdx.x] = b2[threadIdx.x];
    }
}

// ---------------- streaming fp32 -> bf16 hi/lo split of x ------------------
__global__ __launch_bounds__(256) void convert_x(const float* __restrict__ x,
                                                 bf16* __restrict__ xh,
                                                 bf16* __restrict__ xl) {
    const size_t i8 = ((size_t)blockIdx.x * 256 + threadIdx.x) * 8;
    float4 v0 = *(const float4*)(x + i8);
    float4 v1 = *(const float4*)(x + i8 + 4);
    uint32_t hw[4], lw[4];
    hw[0] = splitpk_hi(v0.x, v0.y, lw[0]);
    hw[1] = splitpk_hi(v0.z, v0.w, lw[1]);
    hw[2] = splitpk_hi(v1.x, v1.y, lw[2]);
    hw[3] = splitpk_hi(v1.z, v1.w, lw[3]);
    *(uint4*)(xh + i8) = make_uint4(hw[0], hw[1], hw[2], hw[3]);
    *(uint4*)(xl + i8) = make_uint4(lw[0], lw[1], lw[2], lw[3]);
}

// ---------------- softmax over split-K partials -> bf16 hi/lo beta --------
__global__ __launch_bounds__(256) void softmax_kernel() {
    const int row = blockIdx.x;  // b*Cn + i
    const int b = row >> 8, i = row & 255;
    const int j = threadIdx.x;
    float v = 0.f;
#pragma unroll
    for (int sp = 0; sp < SPLITS; ++sp)
        v += g_sPart[((size_t)(b * SPLITS + sp) << 16) + i * Cn + j];
    __shared__ float red[256];
    red[j] = v;
    __syncthreads();
    for (int s = 128; s > 0; s >>= 1) {
        if (j < s) red[j] = fmaxf(red[j], red[j + s]);
        __syncthreads();
    }
    const float mx = red[0];
    __syncthreads();
    const float e = expf(v - mx);
    red[j] = e;
    __syncthreads();
    for (int s = 128; s > 0; s >>= 1) {
        if (j < s) red[j] += red[j + s];
        __syncthreads();
    }
    const float r = e / red[0];
    bf16 h = __float2bfloat16(r);
    bf16 l = __float2bfloat16(r - __bfloat162float(h));
    g_betah[(size_t)row * Cn + j] = h;
    g_betal[(size_t)row * Cn + j] = l;
}

// -------------------------------------------------------------------------
extern "C" void kernel_launch(void* const* d_in, const int* in_sizes, int n_in,
                              void* d_out, int out_size) {
    const float* x = (const float*)d_in[0];
    const float* Wf = (const float*)d_in[1];
    const float* bfp = (const float*)d_in[2];
    const float* Wg = (const float*)d_in[3];
    const float* bg = (const float*)d_in[4];
    const float* Wh = (const float*)d_in[5];
    const float* bh = (const float*)d_in[6];
    const float* Wo = (const float*)d_in[7];
    const float* bo = (const float*)d_in[8];
    float* out = (float*)d_out;

    bf16 *Xh, *Xl, *FGHh, *FGHl, *aTh, *aTl, *Wsh, *Wsl, *betah, *betal;
    float *sPart, *bstk;
    cudaGetSymbolAddress((void**)&Xh, g_Xh);
    cudaGetSymbolAddress((void**)&Xl, g_Xl);
    cudaGetSymbolAddress((void**)&FGHh, g_FGHh);
    cudaGetSymbolAddress((void**)&FGHl, g_FGHl);
    cudaGetSymbolAddress((void**)&aTh, g_aTh);
    cudaGetSymbolAddress((void**)&aTl, g_aTl);
    cudaGetSymbolAddress((void**)&Wsh, g_Wsh);
    cudaGetSymbolAddress((void**)&Wsl, g_Wsl);
    cudaGetSymbolAddress((void**)&betah, g_betah);
    cudaGetSymbolAddress((void**)&betal, g_betal);
    cudaGetSymbolAddress((void**)&sPart, g_sPart);
    cudaGetSymbolAddress((void**)&bstk, g_bstk);

    const int SMSZ = 131072;
    cudaFuncSetAttribute(gemm_bf<false, true, true>,
                         cudaFuncAttributeMaxDynamicSharedMemorySize, SMSZ);
    cudaFuncSetAttribute(gemm_bf<true, true, false>,
                         cudaFuncAttributeMaxDynamicSharedMemorySize, SMSZ);
    cudaFuncSetAttribute(gemm_bf<false, false, true>,
                         cudaFuncAttributeMaxDynamicSharedMemorySize, SMSZ);
    cudaFuncSetAttribute(gemm_bf<false, false, false>,
                         cudaFuncAttributeMaxDynamicSharedMemorySize, SMSZ);

    // 0) weights -> bf16 hi/lo (stacked), biases -> stacked
    prep_weights<<<512, 256>>>(Wf, Wg, Wh, Wo, bfp, bg, bh);

    // 1) x -> hi/lo (same [c][n] layout, no transpose)
    convert_x<<<(Bn * Cn * Nn) / (256 * 8), 256>>>(x, Xh, Xl);

    // 2) merged conv F,G,H: D[m][n] = sum_k Wstk[m][k] x[k][n]; B trans-mode
    gemm_bf<false, true, true><<<dim3(Nn / 128, 6, Bn), 256, SMSZ>>>(
        Wsh, Wsl, Xh, Xl, Cn, Nn, Cn, 1, 0, CN, 3 * CN, bstk, FGHh, FGHl, Nn);

    // 3) s partials: D[i][j] = sum_n Gr[n][i] Fr[n][j]; both trans-mode,
    //    reading the conv output flat buffers as [n'][c] (raw reshape view)
    gemm_bf<true, true, false><<<dim3(2, 2, Bn * SPLITS), 256, SMSZ>>>(
        FGHh + CN, FGHl + CN, FGHh, FGHl, Cn, Cn, Nn / SPLITS, SPLITS,
        3 * CN, 3 * CN, (size_t)Cn * Cn, nullptr, sPart, nullptr, Cn);

    // 4) softmax -> beta bf16 hi/lo
    softmax_kernel<<<Bn * Cn, 256>>>();

    // 5) attnT[p][i] = sum_j Hr[p][j] beta[i][j]; both K-major
    gemm_bf<false, false, true><<<dim3(Cn / 128, Nn / 128, Bn), 256, SMSZ>>>(
        FGHh + 2 * CN, FGHl + 2 * CN, betah, betal, Cn, Cn, Cn, 1,
        3 * CN, (size_t)Cn * Cn, CN, nullptr, aTh, aTl, Cn);

    // 6) final conv: y[o][p] = sum_i Wo[o][i] attnT[p][i] -> d_out fp32
    gemm_bf<false, false, false><<<dim3(Nn / 128, Cn / 128, Bn), 256, SMSZ>>>(
        Wsh + 3 * (size_t)Cn * Cn, Wsl + 3 * (size_t)Cn * Cn, aTh, aTl,
        Cn, Cn, Cn, 1, 0, CN, CN, bo, out, nullptr, Nn);
}

// round 9
// speedup vs baseline: 2.6628x; 1.0182x over previous
#include <cuda_runtime.h>
#include <cuda_bf16.h>
#include <cstdint>
#include <cstddef>

typedef unsigned long long u64;
typedef __nv_bfloat16 bf16;

#define Bn 8
#define Cn 256
#define Nn 4096
#define SPLITS 8
#define CN ((size_t)Cn * Nn)
#define STG 32768  // bytes per pipeline stage (A 16K + B 16K)

// ---------------- device scratch (no allocations allowed) ----------------
__device__ bf16 g_Xh[Bn * Cn * Nn], g_Xl[Bn * Cn * Nn];     // x hi/lo [b][c][n]
__device__ bf16 g_FGHh[Bn * 3 * Cn * Nn], g_FGHl[Bn * 3 * Cn * Nn];
__device__ bf16 g_aTh[Bn * Nn * Cn], g_aTl[Bn * Nn * Cn];   // attnT [b][n'][i]
__device__ bf16 g_Wsh[4 * Cn * Cn], g_Wsl[4 * Cn * Cn];     // stacked weights
__device__ float g_bstk[3 * Cn];
__device__ float g_sPart[SPLITS * Bn * Cn * Cn];
__device__ bf16 g_betah[Bn * Cn * Cn], g_betal[Bn * Cn * Cn];

// ---------------- helpers -------------------------------------------------
#define SWZ(o) ((o) ^ (((o) >> 3) & 0x70))

__device__ __forceinline__ uint32_t s2u(const void* p) {
    uint32_t a;
    asm("{ .reg .u64 t; cvta.to.shared.u64 t, %1; cvt.u32.u64 %0, t; }"
        : "=r"(a) : "l"(p));
    return a;
}
__device__ __forceinline__ uint32_t splitpk_hi(float a, float b, uint32_t& lo) {
    bf16 h0 = __float2bfloat16(a), h1 = __float2bfloat16(b);
    bf16 l0 = __float2bfloat16(a - __bfloat162float(h0));
    bf16 l1 = __float2bfloat16(b - __bfloat162float(h1));
    lo = (uint32_t)__bfloat16_as_ushort(l0) |
         ((uint32_t)__bfloat16_as_ushort(l1) << 16);
    return (uint32_t)__bfloat16_as_ushort(h0) |
           ((uint32_t)__bfloat16_as_ushort(h1) << 16);
}
__device__ __forceinline__ void ldm4(uint32_t* r, uint32_t addr) {
    asm volatile(
        "ldmatrix.sync.aligned.m8n8.x4.shared.b16 {%0,%1,%2,%3}, [%4];"
        : "=r"(r[0]), "=r"(r[1]), "=r"(r[2]), "=r"(r[3]) : "r"(addr));
}
__device__ __forceinline__ void ldm4t(uint32_t* r, uint32_t addr) {
    asm volatile(
        "ldmatrix.sync.aligned.m8n8.x4.trans.shared.b16 {%0,%1,%2,%3}, [%4];"
        : "=r"(r[0]), "=r"(r[1]), "=r"(r[2]), "=r"(r[3]) : "r"(addr));
}
__device__ __forceinline__ void mma16816(float* c, const uint32_t* a,
                                         uint32_t b0, uint32_t b1) {
    asm volatile(
        "mma.sync.aligned.m16n8k16.row.col.f32.bf16.bf16.f32 "
        "{%0,%1,%2,%3}, {%4,%5,%6,%7}, {%8,%9}, {%0,%1,%2,%3};"
        : "+f"(c[0]), "+f"(c[1]), "+f"(c[2]), "+f"(c[3])
        : "r"(a[0]), "r"(a[1]), "r"(a[2]), "r"(a[3]), "r"(b0), "r"(b1));
}
__device__ __forceinline__ void cpa16(uint32_t dst, const void* src) {
    asm volatile("cp.async.cg.shared.global [%0], [%1], 16;"
                 :: "r"(dst), "l"(src) : "memory");
}

// ---------------- HMMA GEMM, all-bf16, 3-stage cp.async, BK=32 ------------
// D[m0:128][n0:128] = sum_k A[m][k]*B[n][k]; hi/lo split, 3-mma emulation
// non-trans smem row (128B) = [hi 32k | lo 32k]; trans = 2 col-panels x hi/lo
template <bool AT, bool BT, bool OB16>
__global__ __launch_bounds__(256, 2)
void gemm_bf(const bf16* __restrict__ Ah, const bf16* __restrict__ Al,
             const bf16* __restrict__ Bh, const bf16* __restrict__ Bl,
             size_t sA, size_t sB, int K, int splits,
             size_t Abat, size_t Bbat, size_t Obat,
             const float* __restrict__ bias, void* Oh_, void* Ol_, size_t sO) {
    extern __shared__ __align__(128) char smem[];
    const int tid = threadIdx.x, lane = tid & 31, wid = tid >> 5;
    const int wm = wid >> 2, wn = wid & 3;  // 2x4 warp grid, 64x32 tiles
    const int z = blockIdx.z, b = z / splits, sp = z - b * splits;
    const int kb = sp * K;
    const int m0 = blockIdx.y * 128, n0 = blockIdx.x * 128;
    const uint32_t sb = s2u(smem);

    const bf16* A0 = AT ? (Ah + Abat * b + (size_t)kb * sA + m0)
                        : (Ah + Abat * b + (size_t)m0 * sA + kb);
    const bf16* A1 = AT ? (Al + Abat * b + (size_t)kb * sA + m0)
                        : (Al + Abat * b + (size_t)m0 * sA + kb);
    const bf16* B0 = BT ? (Bh + Bbat * b + (size_t)kb * sB + n0)
                        : (Bh + Bbat * b + (size_t)n0 * sB + kb);
    const bf16* B1 = BT ? (Bl + Bbat * b + (size_t)kb * sB + n0)
                        : (Bl + Bbat * b + (size_t)n0 * sB + kb);

#define LOAD_OP(TR, off, Phi, Plo, stride, s)                                 \
    if constexpr (TR) {                                                       \
        _Pragma("unroll") for (int i = 0; i < 4; ++i) {                       \
            int ch = tid + 256 * i;                                           \
            int kr = ch >> 5, rest = ch & 31;                                 \
            int hl = rest >> 4, cq = rest & 15;                               \
            uint32_t o = hl * 8192 + (cq >> 3) * 4096 +                       \
                         SWZ(kr * 128 + (cq & 7) * 16);                       \
            const bf16* src = (hl ? (Plo) : (Phi)) +                          \
                              (size_t)((s) * 32 + kr) * (stride) + cq * 8;    \
            cpa16(bb + (off) + o, src);                                       \
        }                                                                     \
    } else {                                                                  \
        _Pragma("unroll") for (int i = 0; i < 4; ++i) {                       \
            int ch = tid + 256 * i;                                           \
            int r = ch >> 3, hl = (ch >> 2) & 1, q = ch & 3;                  \
            uint32_t o = SWZ(r * 128 + hl * 64 + q * 16);                     \
            const bf16* src = (hl ? (Plo) : (Phi)) +                          \
                              (size_t)r * (stride) + (s) * 32 + q * 8;        \
            cpa16(bb + (off) + o, src);                                       \
        }                                                                     \
    }

#define LOAD_SLAB(s, stg)                                                     \
    {                                                                         \
        const uint32_t bb = sb + (stg) * STG;                                 \
        LOAD_OP(AT, 0, A0, A1, sA, s);                                        \
        LOAD_OP(BT, 16384, B0, B1, sB, s);                                    \
        asm volatile("cp.async.commit_group;" ::: "memory");                  \
    }

    float acc[4][4][4] = {};
    const int NS = K / 32;
    LOAD_SLAB(0, 0);
    LOAD_SLAB(1, 1);

    for (int s = 0; s < NS; ++s) {
        const int stg = s % 3;
        if (s + 2 < NS) {
            LOAD_SLAB(s + 2, (s + 2) % 3);
            asm volatile("cp.async.wait_group 2;" ::: "memory");
        } else if (s + 1 < NS) {
            asm volatile("cp.async.wait_group 1;" ::: "memory");
        } else {
            asm volatile("cp.async.wait_group 0;" ::: "memory");
        }
        __syncthreads();

        const uint32_t base = sb + stg * STG;
        const int trow = lane & 7, tsel = lane >> 3;
#pragma unroll
        for (int kk = 0; kk < 2; ++kk) {
            uint32_t aH[4][4], aL[4][4];
#pragma unroll
            for (int mt = 0; mt < 4; ++mt) {
                if constexpr (AT) {
                    int krow = kk * 16 + (tsel >> 1) * 8 + trow;
                    int mcol = wm * 64 + mt * 16 + (tsel & 1) * 8;
                    uint32_t o = (mcol >> 6) * 4096 +
                                 SWZ(krow * 128 + (mcol & 63) * 2);
                    ldm4t(aH[mt], base + o);
                    ldm4t(aL[mt], base + 8192 + o);
                } else {
                    int mr = wm * 64 + mt * 16 + (tsel & 1) * 8 + trow;
                    int kby = kk * 32 + (tsel >> 1) * 16;
                    ldm4(aH[mt], base + SWZ(mr * 128 + kby));
                    ldm4(aL[mt], base + SWZ(mr * 128 + 64 + kby));
                }
            }
#pragma unroll
            for (int np = 0; np < 2; ++np) {
                uint32_t bH[4], bL[4];
                if constexpr (BT) {
                    int krow = kk * 16 + (tsel & 1) * 8 + trow;
                    int ncol = wn * 32 + np * 16 + (tsel >> 1) * 8;
                    uint32_t o = (ncol >> 6) * 4096 +
                                 SWZ(krow * 128 + (ncol & 63) * 2);
                    ldm4t(bH, base + 16384 + o);
                    ldm4t(bL, base + 16384 + 8192 + o);
                } else {
                    int nr = wn * 32 + np * 16 + (tsel >> 1) * 8 + trow;
                    int kby = kk * 32 + (tsel & 1) * 16;
                    ldm4(bH, base + 16384 + SWZ(nr * 128 + kby));
                    ldm4(bL, base + 16384 + SWZ(nr * 128 + 64 + kby));
                }
#pragma unroll
                for (int mt = 0; mt < 4; ++mt)
#pragma unroll
                    for (int j = 0; j < 2; ++j) {
                        float* c = acc[mt][np * 2 + j];
                        mma16816(c, aH[mt], bH[2 * j], bH[2 * j + 1]);
                        mma16816(c, aH[mt], bL[2 * j], bL[2 * j + 1]);
                        mma16816(c, aL[mt], bH[2 * j], bH[2 * j + 1]);
                    }
            }
        }
        __syncthreads();
    }

    // ---- epilogue
#pragma unroll
    for (int mt = 0; mt < 4; ++mt) {
        const int r0 = m0 + wm * 64 + mt * 16 + (lane >> 2);
        const float bz0 = bias ? bias[r0] : 0.f;
        const float bz1 = bias ? bias[r0 + 8] : 0.f;
#pragma unroll
        for (int nt = 0; nt < 4; ++nt) {
            const int col = n0 + wn * 32 + nt * 8 + 2 * (lane & 3);
            const float* c = acc[mt][nt];
            if constexpr (OB16) {
                bf16* oh = (bf16*)Oh_ + Obat * z;
                bf16* ol = (bf16*)Ol_ + Obat * z;
                uint32_t lo0, lo1;
                uint32_t hi0 = splitpk_hi(c[0] + bz0, c[1] + bz0, lo0);
                uint32_t hi1 = splitpk_hi(c[2] + bz1, c[3] + bz1, lo1);
                *(uint32_t*)(oh + (size_t)r0 * sO + col) = hi0;
                *(uint32_t*)(ol + (size_t)r0 * sO + col) = lo0;
                *(uint32_t*)(oh + (size_t)(r0 + 8) * sO + col) = hi1;
                *(uint32_t*)(ol + (size_t)(r0 + 8) * sO + col) = lo1;
            } else {
                float* o = (float*)Oh_ + Obat * z;
                *(float2*)(o + (size_t)r0 * sO + col) =
                    make_float2(c[0] + bz0, c[1] + bz0);
                *(float2*)(o + (size_t)(r0 + 8) * sO + col) =
                    make_float2(c[2] + bz1, c[3] + bz1);
            }
        }
    }
}

// ---------------- prep: split 4 weight matrices + stack biases ------------
__global__ __launch_bounds__(256) void prep_weights(
    const float* __restrict__ Wf, const float* __restrict__ Wg,
    const float* __restrict__ Wh, const float* __restrict__ Wo,
    const float* __restrict__ b0, const float* __restrict__ b1,
    const float* __restrict__ b2) {
    int idx = blockIdx.x * 256 + threadIdx.x;  // pair index, 4*32768 total
    const float* W = (idx >> 15) == 0 ? Wf
                     : (idx >> 15) == 1 ? Wg
                     : (idx >> 15) == 2 ? Wh : Wo;
    int p = idx & 32767;
    uint32_t lo, hi = splitpk_hi(W[2 * p], W[2 * p + 1], lo);
    ((uint32_t*)g_Wsh)[idx] = hi;
    ((uint32_t*)g_Wsl)[idx] = lo;
    if (blockIdx.x == 0) {
        g_bstk[threadIdx.x] = b0[threadIdx.x];
        g_bstk[256 + threadIdx.x] = b1[threadIdx.x];
        g_bstk[512 + threadIdx.x] = b2[threadIdx.x];
    }
}

// ---------------- streaming fp32 -> bf16 hi/lo split of x ------------------
__global__ __launch_bounds__(256) void convert_x(const float* __restrict__ x,
                                                 bf16* __restrict__ xh,
                                                 bf16* __restrict__ xl) {
    const size_t i8 = ((size_t)blockIdx.x * 256 + threadIdx.x) * 8;
    float4 v0 = *(const float4*)(x + i8);
    float4 v1 = *(const float4*)(x + i8 + 4);
    uint32_t hw[4], lw[4];
    hw[0] = splitpk_hi(v0.x, v0.y, lw[0]);
    hw[1] = splitpk_hi(v0.z, v0.w, lw[1]);
    hw[2] = splitpk_hi(v1.x, v1.y, lw[2]);
    hw[3] = splitpk_hi(v1.z, v1.w, lw[3]);
    *(uint4*)(xh + i8) = make_uint4(hw[0], hw[1], hw[2], hw[3]);
    *(uint4*)(xl + i8) = make_uint4(lw[0], lw[1], lw[2], lw[3]);
}

// ---------------- softmax over split-K partials -> bf16 hi/lo beta --------
__global__ __launch_bounds__(256) void softmax_kernel() {
    const int row = blockIdx.x;  // b*Cn + i
    const int b = row >> 8, i = row & 255;
    const int j = threadIdx.x;
    float v = 0.f;
#pragma unroll
    for (int sp = 0; sp < SPLITS; ++sp)
        v += g_sPart[((size_t)(b * SPLITS + sp) << 16) + i * Cn + j];
    __shared__ float red[256];
    red[j] = v;
    __syncthreads();
    for (int s = 128; s > 0; s >>= 1) {
        if (j < s) red[j] = fmaxf(red[j], red[j + s]);
        __syncthreads();
    }
    const float mx = red[0];
    __syncthreads();
    const float e = expf(v - mx);
    red[j] = e;
    __syncthreads();
    for (int s = 128; s > 0; s >>= 1) {
        if (j < s) red[j] += red[j + s];
        __syncthreads();
    }
    const float r = e / red[0];
    bf16 h = __float2bfloat16(r);
    bf16 l = __float2bfloat16(r - __bfloat162float(h));
    g_betah[(size_t)row * Cn + j] = h;
    g_betal[(size_t)row * Cn + j] = l;
}

// -------------------------------------------------------------------------
extern "C" void kernel_launch(void* const* d_in, const int* in_sizes, int n_in,
                              void* d_out, int out_size) {
    const float* x = (const float*)d_in[0];
    const float* Wf = (const float*)d_in[1];
    const float* bfp = (const float*)d_in[2];
    const float* Wg = (const float*)d_in[3];
    const float* bg = (const float*)d_in[4];
    const float* Wh = (const float*)d_in[5];
    const float* bh = (const float*)d_in[6];
    const float* Wo = (const float*)d_in[7];
    const float* bo = (const float*)d_in[8];
    float* out = (float*)d_out;

    bf16 *Xh, *Xl, *FGHh, *FGHl, *aTh, *aTl, *Wsh, *Wsl, *betah, *betal;
    float *sPart, *bstk;
    cudaGetSymbolAddress((void**)&Xh, g_Xh);
    cudaGetSymbolAddress((void**)&Xl, g_Xl);
    cudaGetSymbolAddress((void**)&FGHh, g_FGHh);
    cudaGetSymbolAddress((void**)&FGHl, g_FGHl);
    cudaGetSymbolAddress((void**)&aTh, g_aTh);
    cudaGetSymbolAddress((void**)&aTl, g_aTl);
    cudaGetSymbolAddress((void**)&Wsh, g_Wsh);
    cudaGetSymbolAddress((void**)&Wsl, g_Wsl);
    cudaGetSymbolAddress((void**)&betah, g_betah);
    cudaGetSymbolAddress((void**)&betal, g_betal);
    cudaGetSymbolAddress((void**)&sPart, g_sPart);
    cudaGetSymbolAddress((void**)&bstk, g_bstk);

    const int SMSZ = 3 * STG;  // 98304
    cudaFuncSetAttribute(gemm_bf<false, true, true>,
                         cudaFuncAttributeMaxDynamicSharedMemorySize, SMSZ);
    cudaFuncSetAttribute(gemm_bf<true, true, false>,
                         cudaFuncAttributeMaxDynamicSharedMemorySize, SMSZ);
    cudaFuncSetAttribute(gemm_bf<false, false, true>,
                         cudaFuncAttributeMaxDynamicSharedMemorySize, SMSZ);
    cudaFuncSetAttribute(gemm_bf<false, false, false>,
                         cudaFuncAttributeMaxDynamicSharedMemorySize, SMSZ);

    // 0) weights -> bf16 hi/lo (stacked), biases -> stacked
    prep_weights<<<512, 256>>>(Wf, Wg, Wh, Wo, bfp, bg, bh);

    // 1) x -> hi/lo (same [c][n] layout, no transpose)
    convert_x<<<(Bn * Cn * Nn) / (256 * 8), 256>>>(x, Xh, Xl);

    // 2) merged conv F,G,H: D[m][n] = sum_k Wstk[m][k] x[k][n]; B trans-mode
    gemm_bf<false, true, true><<<dim3(Nn / 128, 6, Bn), 256, SMSZ>>>(
        Wsh, Wsl, Xh, Xl, Cn, Nn, Cn, 1, 0, CN, 3 * CN, bstk, FGHh, FGHl, Nn);

    // 3) s partials: D[i][j] = sum_n Gr[n][i] Fr[n][j]; both trans-mode,
    //    reading the conv output flat buffers as [n'][c] (raw reshape view)
    gemm_bf<true, true, false><<<dim3(2, 2, Bn * SPLITS), 256, SMSZ>>>(
        FGHh + CN, FGHl + CN, FGHh, FGHl, Cn, Cn, Nn / SPLITS, SPLITS,
        3 * CN, 3 * CN, (size_t)Cn * Cn, nullptr, sPart, nullptr, Cn);

    // 4) softmax -> beta bf16 hi/lo
    softmax_kernel<<<Bn * Cn, 256>>>();

    // 5) attnT[p][i] = sum_j Hr[p][j] beta[i][j]; both K-major
    gemm_bf<false, false, true><<<dim3(Cn / 128, Nn / 128, Bn), 256, SMSZ>>>(
        FGHh + 2 * CN, FGHl + 2 * CN, betah, betal, Cn, Cn, Cn, 1,
        3 * CN, (size_t)Cn * Cn, CN, nullptr, aTh, aTl, Cn);

    // 6) final conv: y[o][p] = sum_i Wo[o][i] attnT[p][i] -> d_out fp32
    gemm_bf<false, false, false><<<dim3(Nn / 128, Cn / 128, Bn), 256, SMSZ>>>(
        Wsh + 3 * (size_t)Cn * Cn, Wsl + 3 * (size_t)Cn * Cn, aTh, aTl,
        Cn, Cn, Cn, 1, 0, CN, CN, bo, out, nullptr, Nn);
}

// round 10
// speedup vs baseline: 2.6692x; 1.0024x over previous
#include <cuda_runtime.h>
#include <cuda_bf16.h>
#include <cstdint>
#include <cstddef>

typedef unsigned long long u64;
typedef __nv_bfloat16 bf16;

#define Bn 8
#define Cn 256
#define Nn 4096
#define SPLITS 8
#define CN ((size_t)Cn * Nn)
#define STG 32768  // bytes per pipeline stage (A 16K + B 16K)

// ---------------- device scratch (no allocations allowed) ----------------
__device__ bf16 g_Xh[Bn * Cn * Nn], g_Xl[Bn * Cn * Nn];     // x hi/lo [b][c][n]
__device__ bf16 g_FGHh[Bn * 3 * Cn * Nn], g_FGHl[Bn * 3 * Cn * Nn];
__device__ bf16 g_aTh[Bn * Nn * Cn], g_aTl[Bn * Nn * Cn];   // attnT [b][n'][i]
__device__ bf16 g_Wsh[4 * Cn * Cn], g_Wsl[4 * Cn * Cn];     // stacked weights
__device__ float g_bstk[3 * Cn];
__device__ float g_sPart[SPLITS * Bn * Cn * Cn];
__device__ bf16 g_betah[Bn * Cn * Cn], g_betal[Bn * Cn * Cn];

// ---------------- helpers -------------------------------------------------
#define SWZ(o) ((o) ^ (((o) >> 3) & 0x70))

__device__ __forceinline__ uint32_t s2u(const void* p) {
    uint32_t a;
    asm("{ .reg .u64 t; cvta.to.shared.u64 t, %1; cvt.u32.u64 %0, t; }"
        : "=r"(a) : "l"(p));
    return a;
}
__device__ __forceinline__ uint32_t splitpk_hi(float a, float b, uint32_t& lo) {
    bf16 h0 = __float2bfloat16(a), h1 = __float2bfloat16(b);
    bf16 l0 = __float2bfloat16(a - __bfloat162float(h0));
    bf16 l1 = __float2bfloat16(b - __bfloat162float(h1));
    lo = (uint32_t)__bfloat16_as_ushort(l0) |
         ((uint32_t)__bfloat16_as_ushort(l1) << 16);
    return (uint32_t)__bfloat16_as_ushort(h0) |
           ((uint32_t)__bfloat16_as_ushort(h1) << 16);
}
__device__ __forceinline__ void ldm4(uint32_t* r, uint32_t addr) {
    asm volatile(
        "ldmatrix.sync.aligned.m8n8.x4.shared.b16 {%0,%1,%2,%3}, [%4];"
        : "=r"(r[0]), "=r"(r[1]), "=r"(r[2]), "=r"(r[3]) : "r"(addr));
}
__device__ __forceinline__ void ldm4t(uint32_t* r, uint32_t addr) {
    asm volatile(
        "ldmatrix.sync.aligned.m8n8.x4.trans.shared.b16 {%0,%1,%2,%3}, [%4];"
        : "=r"(r[0]), "=r"(r[1]), "=r"(r[2]), "=r"(r[3]) : "r"(addr));
}
__device__ __forceinline__ void mma16816(float* c, const uint32_t* a,
                                         uint32_t b0, uint32_t b1) {
    asm volatile(
        "mma.sync.aligned.m16n8k16.row.col.f32.bf16.bf16.f32 "
        "{%0,%1,%2,%3}, {%4,%5,%6,%7}, {%8,%9}, {%0,%1,%2,%3};"
        : "+f"(c[0]), "+f"(c[1]), "+f"(c[2]), "+f"(c[3])
        : "r"(a[0]), "r"(a[1]), "r"(a[2]), "r"(a[3]), "r"(b0), "r"(b1));
}
__device__ __forceinline__ void cpa16(uint32_t dst, const void* src) {
    asm volatile("cp.async.cg.shared.global [%0], [%1], 16;"
                 :: "r"(dst), "l"(src) : "memory");
}

// ---------------- HMMA GEMM, all-bf16, 3-stage cp.async, BK=32 ------------
// D[m0:128][n0:128] = sum_k A[m][k]*B[n][k]; hi/lo split, 3-mma emulation
// non-trans smem row (128B) = [hi 32k | lo 32k]; trans = 2 col-panels x hi/lo
// MMA issue is TERM-MAJOR (hh x8, hl x8, lh x8) to break accumulator chains.
template <bool AT, bool BT, bool OB16>
__global__ __launch_bounds__(256, 2)
void gemm_bf(const bf16* __restrict__ Ah, const bf16* __restrict__ Al,
             const bf16* __restrict__ Bh, const bf16* __restrict__ Bl,
             size_t sA, size_t sB, int K, int splits,
             size_t Abat, size_t Bbat, size_t Obat,
             const float* __restrict__ bias, void* Oh_, void* Ol_, size_t sO) {
    extern __shared__ __align__(128) char smem[];
    const int tid = threadIdx.x, lane = tid & 31, wid = tid >> 5;
    const int wm = wid >> 2, wn = wid & 3;  // 2x4 warp grid, 64x32 tiles
    const int z = blockIdx.z, b = z / splits, sp = z - b * splits;
    const int kb = sp * K;
    const int m0 = blockIdx.y * 128, n0 = blockIdx.x * 128;
    const uint32_t sb = s2u(smem);

    const bf16* A0 = AT ? (Ah + Abat * b + (size_t)kb * sA + m0)
                        : (Ah + Abat * b + (size_t)m0 * sA + kb);
    const bf16* A1 = AT ? (Al + Abat * b + (size_t)kb * sA + m0)
                        : (Al + Abat * b + (size_t)m0 * sA + kb);
    const bf16* B0 = BT ? (Bh + Bbat * b + (size_t)kb * sB + n0)
                        : (Bh + Bbat * b + (size_t)n0 * sB + kb);
    const bf16* B1 = BT ? (Bl + Bbat * b + (size_t)kb * sB + n0)
                        : (Bl + Bbat * b + (size_t)n0 * sB + kb);

#define LOAD_OP(TR, off, Phi, Plo, stride, s)                                 \
    if constexpr (TR) {                                                       \
        _Pragma("unroll") for (int i = 0; i < 4; ++i) {                       \
            int ch = tid + 256 * i;                                           \
            int kr = ch >> 5, rest = ch & 31;                                 \
            int hl = rest >> 4, cq = rest & 15;                               \
            uint32_t o = hl * 8192 + (cq >> 3) * 4096 +                       \
                         SWZ(kr * 128 + (cq & 7) * 16);                       \
            const bf16* src = (hl ? (Plo) : (Phi)) +                          \
                              (size_t)((s) * 32 + kr) * (stride) + cq * 8;    \
            cpa16(bb + (off) + o, src);                                       \
        }                                                                     \
    } else {                                                                  \
        _Pragma("unroll") for (int i = 0; i < 4; ++i) {                       \
            int ch = tid + 256 * i;                                           \
            int r = ch >> 3, hl = (ch >> 2) & 1, q = ch & 3;                  \
            uint32_t o = SWZ(r * 128 + hl * 64 + q * 16);                     \
            const bf16* src = (hl ? (Plo) : (Phi)) +                          \
                              (size_t)r * (stride) + (s) * 32 + q * 8;        \
            cpa16(bb + (off) + o, src);                                       \
        }                                                                     \
    }

#define LOAD_SLAB(s, stg)                                                     \
    {                                                                         \
        const uint32_t bb = sb + (stg) * STG;                                 \
        LOAD_OP(AT, 0, A0, A1, sA, s);                                        \
        LOAD_OP(BT, 16384, B0, B1, sB, s);                                    \
        asm volatile("cp.async.commit_group;" ::: "memory");                  \
    }

    float acc[4][4][4] = {};
    const int NS = K / 32;
    LOAD_SLAB(0, 0);
    LOAD_SLAB(1, 1);

    for (int s = 0; s < NS; ++s) {
        const int stg = s % 3;
        if (s + 1 < NS) {
            asm volatile("cp.async.wait_group 1;" ::: "memory");
        } else {
            asm volatile("cp.async.wait_group 0;" ::: "memory");
        }
        __syncthreads();
        // safe to overwrite stage (s+2)%3: all warps finished reading it
        if (s + 2 < NS) LOAD_SLAB(s + 2, (s + 2) % 3);

        const uint32_t base = sb + stg * STG;
        const int trow = lane & 7, tsel = lane >> 3;
#pragma unroll
        for (int kk = 0; kk < 2; ++kk) {
            uint32_t aH[4][4], aL[4][4];
#pragma unroll
            for (int mt = 0; mt < 4; ++mt) {
                if constexpr (AT) {
                    int krow = kk * 16 + (tsel >> 1) * 8 + trow;
                    int mcol = wm * 64 + mt * 16 + (tsel & 1) * 8;
                    uint32_t o = (mcol >> 6) * 4096 +
                                 SWZ(krow * 128 + (mcol & 63) * 2);
                    ldm4t(aH[mt], base + o);
                    ldm4t(aL[mt], base + 8192 + o);
                } else {
                    int mr = wm * 64 + mt * 16 + (tsel & 1) * 8 + trow;
                    int kby = kk * 32 + (tsel >> 1) * 16;
                    ldm4(aH[mt], base + SWZ(mr * 128 + kby));
                    ldm4(aL[mt], base + SWZ(mr * 128 + 64 + kby));
                }
            }
#pragma unroll
            for (int np = 0; np < 2; ++np) {
                uint32_t bH[4], bL[4];
                if constexpr (BT) {
                    int krow = kk * 16 + (tsel & 1) * 8 + trow;
                    int ncol = wn * 32 + np * 16 + (tsel >> 1) * 8;
                    uint32_t o = (ncol >> 6) * 4096 +
                                 SWZ(krow * 128 + (ncol & 63) * 2);
                    ldm4t(bH, base + 16384 + o);
                    ldm4t(bL, base + 16384 + 8192 + o);
                } else {
                    int nr = wn * 32 + np * 16 + (tsel >> 1) * 8 + trow;
                    int kby = kk * 32 + (tsel & 1) * 16;
                    ldm4(bH, base + 16384 + SWZ(nr * 128 + kby));
                    ldm4(bL, base + 16384 + SWZ(nr * 128 + 64 + kby));
                }
                // term-major: dependent MMAs on the same acc are 8 apart
#pragma unroll
                for (int mt = 0; mt < 4; ++mt)
#pragma unroll
                    for (int j = 0; j < 2; ++j)
                        mma16816(acc[mt][np * 2 + j], aH[mt], bH[2 * j],
                                 bH[2 * j + 1]);
#pragma unroll
                for (int mt = 0; mt < 4; ++mt)
#pragma unroll
                    for (int j = 0; j < 2; ++j)
                        mma16816(acc[mt][np * 2 + j], aH[mt], bL[2 * j],
                                 bL[2 * j + 1]);
#pragma unroll
                for (int mt = 0; mt < 4; ++mt)
#pragma unroll
                    for (int j = 0; j < 2; ++j)
                        mma16816(acc[mt][np * 2 + j], aL[mt], bH[2 * j],
                                 bH[2 * j + 1]);
            }
        }
    }

    // ---- epilogue
#pragma unroll
    for (int mt = 0; mt < 4; ++mt) {
        const int r0 = m0 + wm * 64 + mt * 16 + (lane >> 2);
        const float bz0 = bias ? bias[r0] : 0.f;
        const float bz1 = bias ? bias[r0 + 8] : 0.f;
#pragma unroll
        for (int nt = 0; nt < 4; ++nt) {
            const int col = n0 + wn * 32 + nt * 8 + 2 * (lane & 3);
            const float* c = acc[mt][nt];
            if constexpr (OB16) {
                bf16* oh = (bf16*)Oh_ + Obat * z;
                bf16* ol = (bf16*)Ol_ + Obat * z;
                uint32_t lo0, lo1;
                uint32_t hi0 = splitpk_hi(c[0] + bz0, c[1] + bz0, lo0);
                uint32_t hi1 = splitpk_hi(c[2] + bz1, c[3] + bz1, lo1);
                *(uint32_t*)(oh + (size_t)r0 * sO + col) = hi0;
                *(uint32_t*)(ol + (size_t)r0 * sO + col) = lo0;
                *(uint32_t*)(oh + (size_t)(r0 + 8) * sO + col) = hi1;
                *(uint32_t*)(ol + (size_t)(r0 + 8) * sO + col) = lo1;
            } else {
                float* o = (float*)Oh_ + Obat * z;
                *(float2*)(o + (size_t)r0 * sO + col) =
                    make_float2(c[0] + bz0, c[1] + bz0);
                *(float2*)(o + (size_t)(r0 + 8) * sO + col) =
                    make_float2(c[2] + bz1, c[3] + bz1);
            }
        }
    }
}

// ---------------- prep: split 4 weight matrices + stack biases ------------
__global__ __launch_bounds__(256) void prep_weights(
    const float* __restrict__ Wf, const float* __restrict__ Wg,
    const float* __restrict__ Wh, const float* __restrict__ Wo,
    const float* __restrict__ b0, const float* __restrict__ b1,
    const float* __restrict__ b2) {
    int idx = blockIdx.x * 256 + threadIdx.x;  // pair index, 4*32768 total
    const float* W = (idx >> 15) == 0 ? Wf
                     : (idx >> 15) == 1 ? Wg
                     : (idx >> 15) == 2 ? Wh : Wo;
    int p = idx & 32767;
    uint32_t lo, hi = splitpk_hi(W[2 * p], W[2 * p + 1], lo);
    ((uint32_t*)g_Wsh)[idx] = hi;
    ((uint32_t*)g_Wsl)[idx] = lo;
    if (blockIdx.x == 0) {
        g_bstk[threadIdx.x] = b0[threadIdx.x];
        g_bstk[256 + threadIdx.x] = b1[threadIdx.x];
        g_bstk[512 + threadIdx.x] = b2[threadIdx.x];
    }
}

// ---------------- streaming fp32 -> bf16 hi/lo split of x ------------------
__global__ __launch_bounds__(256) void convert_x(const float* __restrict__ x,
                                                 bf16* __restrict__ xh,
                                                 bf16* __restrict__ xl) {
    const size_t i8 = ((size_t)blockIdx.x * 256 + threadIdx.x) * 8;
    float4 v0 = *(const float4*)(x + i8);
    float4 v1 = *(const float4*)(x + i8 + 4);
    uint32_t hw[4], lw[4];
    hw[0] = splitpk_hi(v0.x, v0.y, lw[0]);
    hw[1] = splitpk_hi(v0.z, v0.w, lw[1]);
    hw[2] = splitpk_hi(v1.x, v1.y, lw[2]);
    hw[3] = splitpk_hi(v1.z, v1.w, lw[3]);
    *(uint4*)(xh + i8) = make_uint4(hw[0], hw[1], hw[2], hw[3]);
    *(uint4*)(xl + i8) = make_uint4(lw[0], lw[1], lw[2], lw[3]);
}

// ---------------- softmax over split-K partials -> bf16 hi/lo beta --------
__global__ __launch_bounds__(256) void softmax_kernel() {
    const int row = blockIdx.x;  // b*Cn + i
    const int b = row >> 8, i = row & 255;
    const int j = threadIdx.x;
    float v = 0.f;
#pragma unroll
    for (int sp = 0; sp < SPLITS; ++sp)
        v += g_sPart[((size_t)(b * SPLITS + sp) << 16) + i * Cn + j];
    __shared__ float red[256];
    red[j] = v;
    __syncthreads();
    for (int s = 128; s > 0; s >>= 1) {
        if (j < s) red[j] = fmaxf(red[j], red[j + s]);
        __syncthreads();
    }
    const float mx = red[0];
    __syncthreads();
    const float e = expf(v - mx);
    red[j] = e;
    __syncthreads();
    for (int s = 128; s > 0; s >>= 1) {
        if (j < s) red[j] += red[j + s];
        __syncthreads();
    }
    const float r = e / red[0];
    bf16 h = __float2bfloat16(r);
    bf16 l = __float2bfloat16(r - __bfloat162float(h));
    g_betah[(size_t)row * Cn + j] = h;
    g_betal[(size_t)row * Cn + j] = l;
}

// -------------------------------------------------------------------------
extern "C" void kernel_launch(void* const* d_in, const int* in_sizes, int n_in,
                              void* d_out, int out_size) {
    const float* x = (const float*)d_in[0];
    const float* Wf = (const float*)d_in[1];
    const float* bfp = (const float*)d_in[2];
    const float* Wg = (const float*)d_in[3];
    const float* bg = (const float*)d_in[4];
    const float* Wh = (const float*)d_in[5];
    const float* bh = (const float*)d_in[6];
    const float* Wo = (const float*)d_in[7];
    const float* bo = (const float*)d_in[8];
    float* out = (float*)d_out;

    bf16 *Xh, *Xl, *FGHh, *FGHl, *aTh, *aTl, *Wsh, *Wsl, *betah, *betal;
    float *sPart, *bstk;
    cudaGetSymbolAddress((void**)&Xh, g_Xh);
    cudaGetSymbolAddress((void**)&Xl, g_Xl);
    cudaGetSymbolAddress((void**)&FGHh, g_FGHh);
    cudaGetSymbolAddress((void**)&FGHl, g_FGHl);
    cudaGetSymbolAddress((void**)&aTh, g_aTh);
    cudaGetSymbolAddress((void**)&aTl, g_aTl);
    cudaGetSymbolAddress((void**)&Wsh, g_Wsh);
    cudaGetSymbolAddress((void**)&Wsl, g_Wsl);
    cudaGetSymbolAddress((void**)&betah, g_betah);
    cudaGetSymbolAddress((void**)&betal, g_betal);
    cudaGetSymbolAddress((void**)&sPart, g_sPart);
    cudaGetSymbolAddress((void**)&bstk, g_bstk);

    const int SMSZ = 3 * STG;  // 98304
    cudaFuncSetAttribute(gemm_bf<false, true, true>,
                         cudaFuncAttributeMaxDynamicSharedMemorySize, SMSZ);
    cudaFuncSetAttribute(gemm_bf<true, true, false>,
                         cudaFuncAttributeMaxDynamicSharedMemorySize, SMSZ);
    cudaFuncSetAttribute(gemm_bf<false, false, true>,
                         cudaFuncAttributeMaxDynamicSharedMemorySize, SMSZ);
    cudaFuncSetAttribute(gemm_bf<false, false, false>,
                         cudaFuncAttributeMaxDynamicSharedMemorySize, SMSZ);

    // 0) weights -> bf16 hi/lo (stacked), biases -> stacked
    prep_weights<<<512, 256>>>(Wf, Wg, Wh, Wo, bfp, bg, bh);

    // 1) x -> hi/lo (same [c][n] layout, no transpose)
    convert_x<<<(Bn * Cn * Nn) / (256 * 8), 256>>>(x, Xh, Xl);

    // 2) merged conv F,G,H: D[m][n] = sum_k Wstk[m][k] x[k][n]; B trans-mode
    gemm_bf<false, true, true><<<dim3(Nn / 128, 6, Bn), 256, SMSZ>>>(
        Wsh, Wsl, Xh, Xl, Cn, Nn, Cn, 1, 0, CN, 3 * CN, bstk, FGHh, FGHl, Nn);

    // 3) s partials: D[i][j] = sum_n Gr[n][i] Fr[n][j]; both trans-mode,
    //    reading the conv output flat buffers as [n'][c] (raw reshape view)
    gemm_bf<true, true, false><<<dim3(2, 2, Bn * SPLITS), 256, SMSZ>>>(
        FGHh + CN, FGHl + CN, FGHh, FGHl, Cn, Cn, Nn / SPLITS, SPLITS,
        3 * CN, 3 * CN, (size_t)Cn * Cn, nullptr, sPart, nullptr, Cn);

    // 4) softmax -> beta bf16 hi/lo
    softmax_kernel<<<Bn * Cn, 256>>>();

    // 5) attnT[p][i] = sum_j Hr[p][j] beta[i][j]; both K-major
    gemm_bf<false, false, true><<<dim3(Cn / 128, Nn / 128, Bn), 256, SMSZ>>>(
        FGHh + 2 * CN, FGHl + 2 * CN, betah, betal, Cn, Cn, Cn, 1,
        3 * CN, (size_t)Cn * Cn, CN, nullptr, aTh, aTl, Cn);

    // 6) final conv: y[o][p] = sum_i Wo[o][i] attnT[p][i] -> d_out fp32
    gemm_bf<false, false, false><<<dim3(Nn / 128, Cn / 128, Bn), 256, SMSZ>>>(
        Wsh + 3 * (size_t)Cn * Cn, Wsl + 3 * (size_t)Cn * Cn, aTh, aTl,
        Cn, Cn, Cn, 1, 0, CN, CN, bo, out, nullptr, Nn);
}

// round 11
// speedup vs baseline: 3.0562x; 1.1450x over previous
#include <cuda_runtime.h>
#include <cuda_bf16.h>
#include <cstdint>
#include <cstddef>

typedef unsigned long long u64;
typedef __nv_bfloat16 bf16;

#define Bn 8
#define Cn 256
#define Nn 4096
#define SPLITS 8
#define CN ((size_t)Cn * Nn)
#define STG 32768  // bytes per pipeline stage (A 16K + B 16K)

// ---------------- device scratch (no allocations allowed) ----------------
__device__ bf16 g_Xh[Bn * Cn * Nn], g_Xl[Bn * Cn * Nn];     // x hi/lo [b][c][n]
__device__ bf16 g_FGHh[Bn * 3 * Cn * Nn], g_FGHl[Bn * 3 * Cn * Nn];
__device__ bf16 g_Wsh[4 * Cn * Cn], g_Wsl[4 * Cn * Cn];     // stacked weights
__device__ bf16 g_Wph[Bn * Cn * Cn], g_Wpl[Bn * Cn * Cn];   // Wo' = Wo x beta
__device__ float g_bstk[3 * Cn];
__device__ float g_sPart[SPLITS * Bn * Cn * Cn];
__device__ bf16 g_betah[Bn * Cn * Cn], g_betal[Bn * Cn * Cn];

// ---------------- helpers -------------------------------------------------
#define SWZ(o) ((o) ^ (((o) >> 3) & 0x70))

__device__ __forceinline__ uint32_t s2u(const void* p) {
    uint32_t a;
    asm("{ .reg .u64 t; cvta.to.shared.u64 t, %1; cvt.u32.u64 %0, t; }"
        : "=r"(a) : "l"(p));
    return a;
}
__device__ __forceinline__ uint32_t splitpk_hi(float a, float b, uint32_t& lo) {
    bf16 h0 = __float2bfloat16(a), h1 = __float2bfloat16(b);
    bf16 l0 = __float2bfloat16(a - __bfloat162float(h0));
    bf16 l1 = __float2bfloat16(b - __bfloat162float(h1));
    lo = (uint32_t)__bfloat16_as_ushort(l0) |
         ((uint32_t)__bfloat16_as_ushort(l1) << 16);
    return (uint32_t)__bfloat16_as_ushort(h0) |
           ((uint32_t)__bfloat16_as_ushort(h1) << 16);
}
__device__ __forceinline__ void ldm4(uint32_t* r, uint32_t addr) {
    asm volatile(
        "ldmatrix.sync.aligned.m8n8.x4.shared.b16 {%0,%1,%2,%3}, [%4];"
        : "=r"(r[0]), "=r"(r[1]), "=r"(r[2]), "=r"(r[3]) : "r"(addr));
}
__device__ __forceinline__ void ldm4t(uint32_t* r, uint32_t addr) {
    asm volatile(
        "ldmatrix.sync.aligned.m8n8.x4.trans.shared.b16 {%0,%1,%2,%3}, [%4];"
        : "=r"(r[0]), "=r"(r[1]), "=r"(r[2]), "=r"(r[3]) : "r"(addr));
}
__device__ __forceinline__ void mma16816(float* c, const uint32_t* a,
                                         uint32_t b0, uint32_t b1) {
    asm volatile(
        "mma.sync.aligned.m16n8k16.row.col.f32.bf16.bf16.f32 "
        "{%0,%1,%2,%3}, {%4,%5,%6,%7}, {%8,%9}, {%0,%1,%2,%3};"
        : "+f"(c[0]), "+f"(c[1]), "+f"(c[2]), "+f"(c[3])
        : "r"(a[0]), "r"(a[1]), "r"(a[2]), "r"(a[3]), "r"(b0), "r"(b1));
}
__device__ __forceinline__ void cpa16(uint32_t dst, const void* src) {
    asm volatile("cp.async.cg.shared.global [%0], [%1], 16;"
                 :: "r"(dst), "l"(src) : "memory");
}

// ---------------- HMMA GEMM, all-bf16, 3-stage cp.async, BK=32 ------------
// D[m0:128][n0:128] = sum_k A[m][k]*B[n][k]; hi/lo split, 3-mma emulation
// non-trans smem row (128B) = [hi 32k | lo 32k]; trans = 2 col-panels x hi/lo
template <bool AT, bool BT, bool OB16>
__global__ __launch_bounds__(256, 2)
void gemm_bf(const bf16* __restrict__ Ah, const bf16* __restrict__ Al,
             const bf16* __restrict__ Bh, const bf16* __restrict__ Bl,
             size_t sA, size_t sB, int K, int splits,
             size_t Abat, size_t Bbat, size_t Obat,
             const float* __restrict__ bias, void* Oh_, void* Ol_, size_t sO) {
    extern __shared__ __align__(128) char smem[];
    const int tid = threadIdx.x, lane = tid & 31, wid = tid >> 5;
    const int wm = wid >> 2, wn = wid & 3;  // 2x4 warp grid, 64x32 tiles
    const int z = blockIdx.z, b = z / splits, sp = z - b * splits;
    const int kb = sp * K;
    const int m0 = blockIdx.y * 128, n0 = blockIdx.x * 128;
    const uint32_t sb = s2u(smem);

    const bf16* A0 = AT ? (Ah + Abat * b + (size_t)kb * sA + m0)
                        : (Ah + Abat * b + (size_t)m0 * sA + kb);
    const bf16* A1 = AT ? (Al + Abat * b + (size_t)kb * sA + m0)
                        : (Al + Abat * b + (size_t)m0 * sA + kb);
    const bf16* B0 = BT ? (Bh + Bbat * b + (size_t)kb * sB + n0)
                        : (Bh + Bbat * b + (size_t)n0 * sB + kb);
    const bf16* B1 = BT ? (Bl + Bbat * b + (size_t)kb * sB + n0)
                        : (Bl + Bbat * b + (size_t)n0 * sB + kb);

#define LOAD_OP(TR, off, Phi, Plo, stride, s)                                 \
    if constexpr (TR) {                                                       \
        _Pragma("unroll") for (int i = 0; i < 4; ++i) {                       \
            int ch = tid + 256 * i;                                           \
            int kr = ch >> 5, rest = ch & 31;                                 \
            int hl = rest >> 4, cq = rest & 15;                               \
            uint32_t o = hl * 8192 + (cq >> 3) * 4096 +                       \
                         SWZ(kr * 128 + (cq & 7) * 16);                       \
            const bf16* src = (hl ? (Plo) : (Phi)) +                          \
                              (size_t)((s) * 32 + kr) * (stride) + cq * 8;    \
            cpa16(bb + (off) + o, src);                                       \
        }                                                                     \
    } else {                                                                  \
        _Pragma("unroll") for (int i = 0; i < 4; ++i) {                       \
            int ch = tid + 256 * i;                                           \
            int r = ch >> 3, hl = (ch >> 2) & 1, q = ch & 3;                  \
            uint32_t o = SWZ(r * 128 + hl * 64 + q * 16);                     \
            const bf16* src = (hl ? (Plo) : (Phi)) +                          \
                              (size_t)r * (stride) + (s) * 32 + q * 8;        \
            cpa16(bb + (off) + o, src);                                       \
        }                                                                     \
    }

#define LOAD_SLAB(s, stg)                                                     \
    {                                                                         \
        const uint32_t bb = sb + (stg) * STG;                                 \
        LOAD_OP(AT, 0, A0, A1, sA, s);                                        \
        LOAD_OP(BT, 16384, B0, B1, sB, s);                                    \
        asm volatile("cp.async.commit_group;" ::: "memory");                  \
    }

    float acc[4][4][4] = {};
    const int NS = K / 32;
    LOAD_SLAB(0, 0);
    LOAD_SLAB(1, 1);

    for (int s = 0; s < NS; ++s) {
        const int stg = s % 3;
        if (s + 1 < NS) {
            asm volatile("cp.async.wait_group 1;" ::: "memory");
        } else {
            asm volatile("cp.async.wait_group 0;" ::: "memory");
        }
        __syncthreads();
        // safe to overwrite stage (s+2)%3: all warps finished reading it
        if (s + 2 < NS) LOAD_SLAB(s + 2, (s + 2) % 3);

        const uint32_t base = sb + stg * STG;
        const int trow = lane & 7, tsel = lane >> 3;
#pragma unroll
        for (int kk = 0; kk < 2; ++kk) {
            uint32_t aH[4][4], aL[4][4];
#pragma unroll
            for (int mt = 0; mt < 4; ++mt) {
                if constexpr (AT) {
                    int krow = kk * 16 + (tsel >> 1) * 8 + trow;
                    int mcol = wm * 64 + mt * 16 + (tsel & 1) * 8;
                    uint32_t o = (mcol >> 6) * 4096 +
                                 SWZ(krow * 128 + (mcol & 63) * 2);
                    ldm4t(aH[mt], base + o);
                    ldm4t(aL[mt], base + 8192 + o);
                } else {
                    int mr = wm * 64 + mt * 16 + (tsel & 1) * 8 + trow;
                    int kby = kk * 32 + (tsel >> 1) * 16;
                    ldm4(aH[mt], base + SWZ(mr * 128 + kby));
                    ldm4(aL[mt], base + SWZ(mr * 128 + 64 + kby));
                }
            }
#pragma unroll
            for (int np = 0; np < 2; ++np) {
                uint32_t bH[4], bL[4];
                if constexpr (BT) {
                    int krow = kk * 16 + (tsel & 1) * 8 + trow;
                    int ncol = wn * 32 + np * 16 + (tsel >> 1) * 8;
                    uint32_t o = (ncol >> 6) * 4096 +
                                 SWZ(krow * 128 + (ncol & 63) * 2);
                    ldm4t(bH, base + 16384 + o);
                    ldm4t(bL, base + 16384 + 8192 + o);
                } else {
                    int nr = wn * 32 + np * 16 + (tsel >> 1) * 8 + trow;
                    int kby = kk * 32 + (tsel & 1) * 16;
                    ldm4(bH, base + 16384 + SWZ(nr * 128 + kby));
                    ldm4(bL, base + 16384 + SWZ(nr * 128 + 64 + kby));
                }
                // term-major: dependent MMAs on the same acc are 8 apart
#pragma unroll
                for (int mt = 0; mt < 4; ++mt)
#pragma unroll
                    for (int j = 0; j < 2; ++j)
                        mma16816(acc[mt][np * 2 + j], aH[mt], bH[2 * j],
                                 bH[2 * j + 1]);
#pragma unroll
                for (int mt = 0; mt < 4; ++mt)
#pragma unroll
                    for (int j = 0; j < 2; ++j)
                        mma16816(acc[mt][np * 2 + j], aH[mt], bL[2 * j],
                                 bL[2 * j + 1]);
#pragma unroll
                for (int mt = 0; mt < 4; ++mt)
#pragma unroll
                    for (int j = 0; j < 2; ++j)
                        mma16816(acc[mt][np * 2 + j], aL[mt], bH[2 * j],
                                 bH[2 * j + 1]);
            }
        }
    }

    // ---- epilogue
#pragma unroll
    for (int mt = 0; mt < 4; ++mt) {
        const int r0 = m0 + wm * 64 + mt * 16 + (lane >> 2);
        const float bz0 = bias ? bias[r0] : 0.f;
        const float bz1 = bias ? bias[r0 + 8] : 0.f;
#pragma unroll
        for (int nt = 0; nt < 4; ++nt) {
            const int col = n0 + wn * 32 + nt * 8 + 2 * (lane & 3);
            const float* c = acc[mt][nt];
            if constexpr (OB16) {
                bf16* oh = (bf16*)Oh_ + Obat * z;
                bf16* ol = (bf16*)Ol_ + Obat * z;
                uint32_t lo0, lo1;
                uint32_t hi0 = splitpk_hi(c[0] + bz0, c[1] + bz0, lo0);
                uint32_t hi1 = splitpk_hi(c[2] + bz1, c[3] + bz1, lo1);
                *(uint32_t*)(oh + (size_t)r0 * sO + col) = hi0;
                *(uint32_t*)(ol + (size_t)r0 * sO + col) = lo0;
                *(uint32_t*)(oh + (size_t)(r0 + 8) * sO + col) = hi1;
                *(uint32_t*)(ol + (size_t)(r0 + 8) * sO + col) = lo1;
            } else {
                float* o = (float*)Oh_ + Obat * z;
                *(float2*)(o + (size_t)r0 * sO + col) =
                    make_float2(c[0] + bz0, c[1] + bz0);
                *(float2*)(o + (size_t)(r0 + 8) * sO + col) =
                    make_float2(c[2] + bz1, c[3] + bz1);
            }
        }
    }
}

// ---------------- prep: split 4 weight matrices + stack biases ------------
__global__ __launch_bounds__(256) void prep_weights(
    const float* __restrict__ Wf, const float* __restrict__ Wg,
    const float* __restrict__ Wh, const float* __restrict__ Wo,
    const float* __restrict__ b0, const float* __restrict__ b1,
    const float* __restrict__ b2) {
    int idx = blockIdx.x * 256 + threadIdx.x;  // pair index, 4*32768 total
    const float* W = (idx >> 15) == 0 ? Wf
                     : (idx >> 15) == 1 ? Wg
                     : (idx >> 15) == 2 ? Wh : Wo;
    int p = idx & 32767;
    uint32_t lo, hi = splitpk_hi(W[2 * p], W[2 * p + 1], lo);
    ((uint32_t*)g_Wsh)[idx] = hi;
    ((uint32_t*)g_Wsl)[idx] = lo;
    if (blockIdx.x == 0) {
        g_bstk[threadIdx.x] = b0[threadIdx.x];
        g_bstk[256 + threadIdx.x] = b1[threadIdx.x];
        g_bstk[512 + threadIdx.x] = b2[threadIdx.x];
    }
}

// ---------------- streaming fp32 -> bf16 hi/lo split of x ------------------
__global__ __launch_bounds__(256) void convert_x(const float* __restrict__ x,
                                                 bf16* __restrict__ xh,
                                                 bf16* __restrict__ xl) {
    const size_t i8 = ((size_t)blockIdx.x * 256 + threadIdx.x) * 8;
    float4 v0 = *(const float4*)(x + i8);
    float4 v1 = *(const float4*)(x + i8 + 4);
    uint32_t hw[4], lw[4];
    hw[0] = splitpk_hi(v0.x, v0.y, lw[0]);
    hw[1] = splitpk_hi(v0.z, v0.w, lw[1]);
    hw[2] = splitpk_hi(v1.x, v1.y, lw[2]);
    hw[3] = splitpk_hi(v1.z, v1.w, lw[3]);
    *(uint4*)(xh + i8) = make_uint4(hw[0], hw[1], hw[2], hw[3]);
    *(uint4*)(xl + i8) = make_uint4(lw[0], lw[1], lw[2], lw[3]);
}

// ---------------- softmax over split-K partials -> bf16 hi/lo beta --------
__global__ __launch_bounds__(256) void softmax_kernel() {
    const int row = blockIdx.x;  // b*Cn + i
    const int b = row >> 8, i = row & 255;
    const int j = threadIdx.x;
    float v = 0.f;
#pragma unroll
    for (int sp = 0; sp < SPLITS; ++sp)
        v += g_sPart[((size_t)(b * SPLITS + sp) << 16) + i * Cn + j];
    __shared__ float red[256];
    red[j] = v;
    __syncthreads();
    for (int s = 128; s > 0; s >>= 1) {
        if (j < s) red[j] = fmaxf(red[j], red[j + s]);
        __syncthreads();
    }
    const float mx = red[0];
    __syncthreads();
    const float e = expf(v - mx);
    red[j] = e;
    __syncthreads();
    for (int s = 128; s > 0; s >>= 1) {
        if (j < s) red[j] += red[j + s];
        __syncthreads();
    }
    const float r = e / red[0];
    bf16 h = __float2bfloat16(r);
    bf16 l = __float2bfloat16(r - __bfloat162float(h));
    g_betah[(size_t)row * Cn + j] = h;
    g_betal[(size_t)row * Cn + j] = l;
}

// -------------------------------------------------------------------------
extern "C" void kernel_launch(void* const* d_in, const int* in_sizes, int n_in,
                              void* d_out, int out_size) {
    const float* x = (const float*)d_in[0];
    const float* Wf = (const float*)d_in[1];
    const float* bfp = (const float*)d_in[2];
    const float* Wg = (const float*)d_in[3];
    const float* bg = (const float*)d_in[4];
    const float* Wh = (const float*)d_in[5];
    const float* bh = (const float*)d_in[6];
    const float* Wo = (const float*)d_in[7];
    const float* bo = (const float*)d_in[8];
    float* out = (float*)d_out;

    bf16 *Xh, *Xl, *FGHh, *FGHl, *Wsh, *Wsl, *Wph, *Wpl, *betah, *betal;
    float *sPart, *bstk;
    cudaGetSymbolAddress((void**)&Xh, g_Xh);
    cudaGetSymbolAddress((void**)&Xl, g_Xl);
    cudaGetSymbolAddress((void**)&FGHh, g_FGHh);
    cudaGetSymbolAddress((void**)&FGHl, g_FGHl);
    cudaGetSymbolAddress((void**)&Wsh, g_Wsh);
    cudaGetSymbolAddress((void**)&Wsl, g_Wsl);
    cudaGetSymbolAddress((void**)&Wph, g_Wph);
    cudaGetSymbolAddress((void**)&Wpl, g_Wpl);
    cudaGetSymbolAddress((void**)&betah, g_betah);
    cudaGetSymbolAddress((void**)&betal, g_betal);
    cudaGetSymbolAddress((void**)&sPart, g_sPart);
    cudaGetSymbolAddress((void**)&bstk, g_bstk);

    const int SMSZ = 3 * STG;  // 98304
    cudaFuncSetAttribute(gemm_bf<false, true, true>,
                         cudaFuncAttributeMaxDynamicSharedMemorySize, SMSZ);
    cudaFuncSetAttribute(gemm_bf<true, true, false>,
                         cudaFuncAttributeMaxDynamicSharedMemorySize, SMSZ);
    cudaFuncSetAttribute(gemm_bf<false, false, false>,
                         cudaFuncAttributeMaxDynamicSharedMemorySize, SMSZ);

    const size_t CC = (size_t)Cn * Cn;

    // 0) weights -> bf16 hi/lo (stacked), biases -> stacked
    prep_weights<<<512, 256>>>(Wf, Wg, Wh, Wo, bfp, bg, bh);

    // 1) x -> hi/lo (same [c][n] layout, no transpose)
    convert_x<<<(Bn * Cn * Nn) / (256 * 8), 256>>>(x, Xh, Xl);

    // 2) merged conv F,G,H: D[m][n] = sum_k Wstk[m][k] x[k][n]; B trans-mode
    gemm_bf<false, true, true><<<dim3(Nn / 128, 6, Bn), 256, SMSZ>>>(
        Wsh, Wsl, Xh, Xl, Cn, Nn, Cn, 1, 0, CN, 3 * CN, bstk, FGHh, FGHl, Nn);

    // 3) s partials: D[i][j] = sum_n Gr[n][i] Fr[n][j]; both trans-mode,
    //    reading the conv output flat buffers as [n'][c] (raw reshape view)
    gemm_bf<true, true, false><<<dim3(2, 2, Bn * SPLITS), 256, SMSZ>>>(
        FGHh + CN, FGHl + CN, FGHh, FGHl, Cn, Cn, Nn / SPLITS, SPLITS,
        3 * CN, 3 * CN, CC, nullptr, sPart, nullptr, Cn);

    // 4) softmax -> beta bf16 hi/lo
    softmax_kernel<<<Bn * Cn, 256>>>();

    // 5) Wo' [o][j] = sum_i Wo[o][i] beta[i][j]  (beta as BT operand)
    gemm_bf<false, true, true><<<dim3(2, 2, Bn), 256, SMSZ>>>(
        Wsh + 3 * CC, Wsl + 3 * CC, betah, betal, Cn, Cn, Cn, 1,
        0, CC, CC, nullptr, Wph, Wpl, Cn);

    // 6) final: y[o][p] = sum_j Wo'[o][j] Hr[p][j] -> d_out fp32 [o][p]
    gemm_bf<false, false, false><<<dim3(Nn / 128, Cn / 128, Bn), 256, SMSZ>>>(
        Wph, Wpl, FGHh + 2 * CN, FGHl + 2 * CN, Cn, Cn, Cn, 1,
        CC, 3 * CN, CN, bo, out, nullptr, Nn);
}